// round 1
// baseline (speedup 1.0000x reference)
#include <cuda_runtime.h>
#include <cuda_bf16.h>

#define EPSV 1e-7f
#define MAXN 50000

// ------------------------- static device scratch ---------------------------
__device__ __align__(16) float2 g_hb  [MAXN * 32];
__device__ __align__(16) float2 g_xtan[MAXN * 32];
__device__ __align__(16) float2 g_P   [MAXN * 32];
__device__ __align__(16) float2 g_Q   [MAXN * 32];
__device__ __align__(16) float  g_nsq [MAXN];
__device__ __align__(16) float  g_agg [MAXN * 64];

// ------------------------------ helpers ------------------------------------
__device__ __forceinline__ float wsum(float v) {
    v += __shfl_xor_sync(0xffffffffu, v, 16);
    v += __shfl_xor_sync(0xffffffffu, v, 8);
    v += __shfl_xor_sync(0xffffffffu, v, 4);
    v += __shfl_xor_sync(0xffffffffu, v, 2);
    v += __shfl_xor_sync(0xffffffffu, v, 1);
    return v;
}

__device__ __forceinline__ float artanh_c(float x) {
    // x >= 0; clip to 1-EPS as reference does
    x = fminf(x, 1.0f - EPSV);
    return 0.5f * __logf(__fdividef(1.0f + x, 1.0f - x));
}

__device__ __forceinline__ float tanh_pos(float x) {
    // x >= 0
    float e = __expf(-2.0f * x);
    return (1.0f - e) * __fdividef(1.0f, 1.0f + e);
}

__device__ __forceinline__ float sigmoidf_(float z) {
    return __fdividef(1.0f, 1.0f + __expf(-z));
}

__device__ __forceinline__ float siluf_(float z) {
    return z * sigmoidf_(z);
}

// ------------------------- K0: zero agg ------------------------------------
__global__ void k_zero(int n4) {
    int i = blockIdx.x * blockDim.x + threadIdx.x;
    float4* p = reinterpret_cast<float4*>(g_agg);
    if (i < n4) p[i] = make_float4(0.f, 0.f, 0.f, 0.f);
}

// --------- K1: HypLinear: hb = expmap(expmap0(logmap0(h)@W.T), bias) --------
// also writes x_tan = logmap0(hb), nsq = ||hb||^2
__global__ void k_node1(const float* __restrict__ h,
                        const float* __restrict__ Wlin,
                        const float* __restrict__ blin, int n) {
    __shared__ float2 sW[64 * 32];      // sW[k*32+t] = {Wlin[2t][k], Wlin[2t+1][k]}
    __shared__ float  sStage[8][64];

    for (int idx = threadIdx.x; idx < 64 * 32; idx += blockDim.x) {
        int k = idx >> 5, t = idx & 31;
        sW[idx] = make_float2(Wlin[(2 * t) * 64 + k], Wlin[(2 * t + 1) * 64 + k]);
    }
    __syncthreads();

    const int lane = threadIdx.x & 31, w = threadIdx.x >> 5;
    const int warpId = blockIdx.x * (blockDim.x >> 5) + w;
    const int nWarps = gridDim.x * (blockDim.x >> 5);

    float2 b2 = make_float2(blin[2 * lane], blin[2 * lane + 1]);

    for (int node = warpId; node < n; node += nWarps) {
        float2 hv = reinterpret_cast<const float2*>(h)[node * 32 + lane];
        float hsq = wsum(hv.x * hv.x + hv.y * hv.y);
        float nh = fmaxf(sqrtf(hsq), EPSV);
        float a = artanh_c(nh) * __fdividef(1.0f, nh);
        float2 lm = make_float2(hv.x * a, hv.y * a);

        sStage[w][2 * lane] = lm.x;
        sStage[w][2 * lane + 1] = lm.y;
        __syncwarp();
        float2 acc = make_float2(0.f, 0.f);
#pragma unroll
        for (int k = 0; k < 64; ++k) {
            float xk = sStage[w][k];
            float2 wv = sW[k * 32 + lane];
            acc.x = fmaf(wv.x, xk, acc.x);
            acc.y = fmaf(wv.y, xk, acc.y);
        }
        __syncwarp();

        // res = expmap0(xt)
        float xsq = wsum(acc.x * acc.x + acc.y * acc.y);
        float nx = fmaxf(sqrtf(xsq), EPSV);
        float s = tanh_pos(nx) * __fdividef(1.0f, nx);
        float2 res = make_float2(acc.x * s, acc.y * s);
        float res2 = wsum(res.x * res.x + res.y * res.y);

        // hb = expmap(res, transp0(res, b)):  u = b*(1-res2)
        float omr = 1.0f - res2;
        float2 u = make_float2(b2.x * omr, b2.y * omr);
        float usq = wsum(u.x * u.x + u.y * u.y);
        float nu = fmaxf(sqrtf(usq), EPSV);
        float lam = 2.0f * __fdividef(1.0f, fmaxf(omr, EPSV));
        float ws = tanh_pos(0.5f * lam * nu) * __fdividef(1.0f, nu);
        float2 wv2 = make_float2(u.x * ws, u.y * ws);

        // mobius_add(res, wv2)
        float y2 = wsum(wv2.x * wv2.x + wv2.y * wv2.y);
        float xy = wsum(res.x * wv2.x + res.y * wv2.y);
        float ca = 1.0f + 2.0f * xy + y2;
        float cb = 1.0f - res2;
        float den = fmaxf(1.0f + 2.0f * xy + res2 * y2, EPSV);
        float inv = __fdividef(1.0f, den);
        float2 hb = make_float2((ca * res.x + cb * wv2.x) * inv,
                                (ca * res.y + cb * wv2.y) * inv);

        float hbsq = wsum(hb.x * hb.x + hb.y * hb.y);
        g_hb[node * 32 + lane] = hb;
        if (lane == 0) g_nsq[node] = hbsq;

        float nb = fmaxf(sqrtf(hbsq), EPSV);
        float at = artanh_c(nb) * __fdividef(1.0f, nb);
        g_xtan[node * 32 + lane] = make_float2(hb.x * at, hb.y * at);
    }
}

// --------- K2: P = hb @ Wa1[:,0:64].T ,  Q = hb @ Wa1[:,64:128].T -----------
__global__ void k_node2(const float* __restrict__ Wa1, int n) {
    __shared__ float2 sA[64 * 32];
    __shared__ float2 sB[64 * 32];
    __shared__ float  sStage[8][64];

    for (int idx = threadIdx.x; idx < 64 * 32; idx += blockDim.x) {
        int k = idx >> 5, t = idx & 31;
        sA[idx] = make_float2(Wa1[(2 * t) * 130 + k],      Wa1[(2 * t + 1) * 130 + k]);
        sB[idx] = make_float2(Wa1[(2 * t) * 130 + 64 + k], Wa1[(2 * t + 1) * 130 + 64 + k]);
    }
    __syncthreads();

    const int lane = threadIdx.x & 31, w = threadIdx.x >> 5;
    const int warpId = blockIdx.x * (blockDim.x >> 5) + w;
    const int nWarps = gridDim.x * (blockDim.x >> 5);

    for (int node = warpId; node < n; node += nWarps) {
        float2 hv = g_hb[node * 32 + lane];
        sStage[w][2 * lane] = hv.x;
        sStage[w][2 * lane + 1] = hv.y;
        __syncwarp();
        float2 accP = make_float2(0.f, 0.f);
        float2 accQ = make_float2(0.f, 0.f);
#pragma unroll
        for (int k = 0; k < 64; ++k) {
            float xk = sStage[w][k];
            float2 wa = sA[k * 32 + lane];
            float2 wb = sB[k * 32 + lane];
            accP.x = fmaf(wa.x, xk, accP.x);
            accP.y = fmaf(wa.y, xk, accP.y);
            accQ.x = fmaf(wb.x, xk, accQ.x);
            accQ.y = fmaf(wb.y, xk, accQ.y);
        }
        __syncwarp();
        g_P[node * 32 + lane] = accP;
        g_Q[node * 32 + lane] = accQ;
    }
}

// --------------------- K3: edge attention + scatter -------------------------
__global__ void k_edge(const int* __restrict__ edges,
                       const float* __restrict__ dist,
                       const float* __restrict__ emask,
                       const float* __restrict__ Wa1,
                       const float* __restrict__ ba1,
                       const float* __restrict__ Wa2,
                       const float* __restrict__ ba2, int E) {
    const int lane = threadIdx.x & 31, w = threadIdx.x >> 5;

    // per-lane constant weights (thread owns hidden dims 2*lane, 2*lane+1)
    float2 wd  = make_float2(Wa1[(2 * lane) * 130 + 128], Wa1[(2 * lane + 1) * 130 + 128]);
    float2 wdd = make_float2(Wa1[(2 * lane) * 130 + 129], Wa1[(2 * lane + 1) * 130 + 129]);
    float2 bb  = make_float2(ba1[2 * lane], ba1[2 * lane + 1]);
    float2 wa2 = make_float2(Wa2[2 * lane], Wa2[2 * lane + 1]);
    float  b2s = ba2[0];

    const int chunks = (E + 31) >> 5;
    const int c0 = blockIdx.x * (blockDim.x >> 5) + w;
    const int nch = gridDim.x * (blockDim.x >> 5);

    for (int ch = c0; ch < chunks; ch += nch) {
        int e = ch * 32 + lane;
        int r = 0, c = 0;
        float dd = 0.f, em = 0.f, sr = 0.f, sc = 0.f;
        if (e < E) {
            r = edges[e];
            c = edges[E + e];
            dd = dist[e];
            em = emask[e];
            sr = g_nsq[r];
            sc = g_nsq[c];
        }
        int cnt = min(32, E - ch * 32);
        for (int i = 0; i < cnt; ++i) {
            int   ri  = __shfl_sync(0xffffffffu, r, i);
            int   ci  = __shfl_sync(0xffffffffu, c, i);
            float di  = __shfl_sync(0xffffffffu, dd, i);
            float emi = __shfl_sync(0xffffffffu, em, i);
            float x2  = __shfl_sync(0xffffffffu, sr, i);
            float y2  = __shfl_sync(0xffffffffu, sc, i);

            float2 hr = g_hb[ri * 32 + lane];
            float2 hc = g_hb[ci * 32 + lane];
            float xy = wsum(hr.x * hc.x + hr.y * hc.y);

            // ||mobius_add(-x,y)||^2 via dots only
            float al = 1.0f - 2.0f * xy + y2;
            float be = 1.0f - x2;
            float num2 = al * al * x2 + be * be * y2 - 2.0f * al * be * xy;
            float den = fmaxf(1.0f - 2.0f * xy + x2 * y2, EPSV);
            float nrm = __fdividef(sqrtf(fmaxf(num2, 0.0f)), den);
            float dh = 2.0f * artanh_c(nrm);

            float2 p = g_P[ri * 32 + lane];
            float2 q = g_Q[ci * 32 + lane];
            float hx = p.x + q.x + dh * wd.x + di * wdd.x + bb.x;
            float hy = p.y + q.y + dh * wd.y + di * wdd.y + bb.y;
            float zx = siluf_(hx), zy = siluf_(hy);
            float z = wsum(zx * wa2.x + zy * wa2.y);
            float score = sigmoidf_(z + b2s) * emi;

            float2 xc = g_xtan[ci * 32 + lane];
            atomicAdd(&g_agg[ri * 64 + 2 * lane],     xc.x * score);
            atomicAdd(&g_agg[ri * 64 + 2 * lane + 1], xc.y * score);
        }
    }
}

// --------- K4: per-node MLP + expmap0/logmap0/silu epilogue -----------------
__global__ void k_node3(const float* __restrict__ Wm1,
                        const float* __restrict__ bm1,
                        const float* __restrict__ Wm2,
                        const float* __restrict__ bm2,
                        float* __restrict__ out, int n) {
    __shared__ float2 sW1[64 * 32];
    __shared__ float2 sW2[64 * 32];
    __shared__ float  sStage[8][64];

    for (int idx = threadIdx.x; idx < 64 * 32; idx += blockDim.x) {
        int k = idx >> 5, t = idx & 31;
        sW1[idx] = make_float2(Wm1[(2 * t) * 64 + k], Wm1[(2 * t + 1) * 64 + k]);
        sW2[idx] = make_float2(Wm2[(2 * t) * 64 + k], Wm2[(2 * t + 1) * 64 + k]);
    }
    __syncthreads();

    const int lane = threadIdx.x & 31, w = threadIdx.x >> 5;
    const int warpId = blockIdx.x * (blockDim.x >> 5) + w;
    const int nWarps = gridDim.x * (blockDim.x >> 5);

    float2 b1 = make_float2(bm1[2 * lane], bm1[2 * lane + 1]);
    float2 b2 = make_float2(bm2[2 * lane], bm2[2 * lane + 1]);

    for (int node = warpId; node < n; node += nWarps) {
        float2 ag;
        ag.x = g_agg[node * 64 + 2 * lane] * 0.01f;
        ag.y = g_agg[node * 64 + 2 * lane + 1] * 0.01f;

        sStage[w][2 * lane] = ag.x;
        sStage[w][2 * lane + 1] = ag.y;
        __syncwarp();
        float2 acc = make_float2(0.f, 0.f);
#pragma unroll
        for (int k = 0; k < 64; ++k) {
            float xk = sStage[w][k];
            float2 wv = sW1[k * 32 + lane];
            acc.x = fmaf(wv.x, xk, acc.x);
            acc.y = fmaf(wv.y, xk, acc.y);
        }
        __syncwarp();
        float2 hid = make_float2(siluf_(acc.x + b1.x), siluf_(acc.y + b1.y));

        sStage[w][2 * lane] = hid.x;
        sStage[w][2 * lane + 1] = hid.y;
        __syncwarp();
        float2 acc2 = make_float2(0.f, 0.f);
#pragma unroll
        for (int k = 0; k < 64; ++k) {
            float xk = sStage[w][k];
            float2 wv = sW2[k * 32 + lane];
            acc2.x = fmaf(wv.x, xk, acc2.x);
            acc2.y = fmaf(wv.y, xk, acc2.y);
        }
        __syncwarp();
        float2 mlp = make_float2(acc2.x + b2.x, acc2.y + b2.y);

        float2 xt = g_xtan[node * 32 + lane];
        float2 y = make_float2(xt.x + mlp.x, xt.y + mlp.y);

        // out1 = expmap0(y)
        float ysq = wsum(y.x * y.x + y.y * y.y);
        float ny = fmaxf(sqrtf(ysq), EPSV);
        float s1 = tanh_pos(ny) * __fdividef(1.0f, ny);
        float2 o1 = make_float2(y.x * s1, y.y * s1);

        // t2 = logmap0(out1)
        float osq = wsum(o1.x * o1.x + o1.y * o1.y);
        float no = fmaxf(sqrtf(osq), EPSV);
        float a2 = artanh_c(no) * __fdividef(1.0f, no);
        float2 t2 = make_float2(o1.x * a2, o1.y * a2);

        // silu
        float2 sl = make_float2(siluf_(t2.x), siluf_(t2.y));

        // expmap0
        float ssq = wsum(sl.x * sl.x + sl.y * sl.y);
        float ns = fmaxf(sqrtf(ssq), EPSV);
        float s3 = tanh_pos(ns) * __fdividef(1.0f, ns);

        reinterpret_cast<float2*>(out)[node * 32 + lane] =
            make_float2(sl.x * s3, sl.y * s3);
    }
}

// ------------------------------- launch -------------------------------------
extern "C" void kernel_launch(void* const* d_in, const int* in_sizes, int n_in,
                              void* d_out, int out_size) {
    const float* h         = (const float*)d_in[0];
    const float* distances = (const float*)d_in[1];
    const int*   edges     = (const int*)  d_in[2];
    // d_in[3] = node_mask (unused by reference)
    const float* edge_mask = (const float*)d_in[4];
    const float* W_lin     = (const float*)d_in[5];
    const float* b_lin     = (const float*)d_in[6];
    const float* Wa1       = (const float*)d_in[7];
    const float* ba1       = (const float*)d_in[8];
    const float* Wa2       = (const float*)d_in[9];
    const float* ba2       = (const float*)d_in[10];
    const float* Wm1       = (const float*)d_in[11];
    const float* bm1       = (const float*)d_in[12];
    const float* Wm2       = (const float*)d_in[13];
    const float* bm2       = (const float*)d_in[14];

    int N = in_sizes[0] / 64;
    int E = in_sizes[1];

    int n4 = N * 16;  // float4 count of agg
    k_zero<<<(n4 + 255) / 256, 256>>>(n4);
    k_node1<<<1024, 256>>>(h, W_lin, b_lin, N);
    k_node2<<<1024, 256>>>(Wa1, N);
    k_edge<<<2048, 256>>>(edges, distances, edge_mask, Wa1, ba1, Wa2, ba2, E);
    k_node3<<<1024, 256>>>(Wm1, bm1, Wm2, bm2, (float*)d_out, N);
}

// round 3
// speedup vs baseline: 1.1206x; 1.1206x over previous
#include <cuda_runtime.h>
#include <cuda_bf16.h>

#define EPSV 1e-7f
#define MAXN 50000

// ------------------------- static device scratch ---------------------------
__device__ __align__(16) float2 g_hb  [MAXN * 32];
__device__ __align__(16) float2 g_xtan[MAXN * 32];
__device__ __align__(16) float2 g_P   [MAXN * 32];   // hb@A.T + ba1 (bias folded)
__device__ __align__(16) float2 g_Q   [MAXN * 32];   // hb@B.T
__device__ __align__(16) float  g_nsq [MAXN];
__device__ __align__(16) float  g_agg [MAXN * 64];

// ------------------------------ helpers ------------------------------------
__device__ __forceinline__ float wredux(float v) {
    v += __shfl_xor_sync(0xffffffffu, v, 16);
    v += __shfl_xor_sync(0xffffffffu, v, 8);
    v += __shfl_xor_sync(0xffffffffu, v, 4);
    v += __shfl_xor_sync(0xffffffffu, v, 2);
    v += __shfl_xor_sync(0xffffffffu, v, 1);
    return v;
}

__device__ __forceinline__ void red_add_v2(float* addr, float a, float b) {
    asm volatile("red.global.add.v2.f32 [%0], {%1, %2};"
                 :: "l"(addr), "f"(a), "f"(b) : "memory");
}

__device__ __forceinline__ float artanh_c(float x) {
    x = fminf(x, 1.0f - EPSV);
    return 0.5f * __logf(__fdividef(1.0f + x, 1.0f - x));
}

__device__ __forceinline__ float tanh_pos(float x) {  // x >= 0
    float e = __expf(-2.0f * x);
    return (1.0f - e) * __fdividef(1.0f, 1.0f + e);
}

__device__ __forceinline__ float sigmoidf_(float z) {
    return __fdividef(1.0f, 1.0f + __expf(-z));
}

__device__ __forceinline__ float siluf_(float z) {
    return z * sigmoidf_(z);
}

// ===== K1 (fused): HypLinear -> hb, nsq, xtan, P(+ba1), Q, zero agg =========
__global__ void __launch_bounds__(256)
k_nodeA(const float* __restrict__ h,
        const float* __restrict__ Wlin,
        const float* __restrict__ blin,
        const float* __restrict__ Wa1,
        const float* __restrict__ ba1, int n) {
    __shared__ float2 sW[64 * 32];   // sW[k*32+t] = {Wlin[2t][k], Wlin[2t+1][k]}
    __shared__ float2 sA[64 * 32];   // Wa1[:, 0:64]
    __shared__ float2 sB[64 * 32];   // Wa1[:, 64:128]

    for (int idx = threadIdx.x; idx < 64 * 32; idx += blockDim.x) {
        int k = idx >> 5, t = idx & 31;
        sW[idx] = make_float2(Wlin[(2 * t) * 64 + k],      Wlin[(2 * t + 1) * 64 + k]);
        sA[idx] = make_float2(Wa1[(2 * t) * 130 + k],      Wa1[(2 * t + 1) * 130 + k]);
        sB[idx] = make_float2(Wa1[(2 * t) * 130 + 64 + k], Wa1[(2 * t + 1) * 130 + 64 + k]);
    }
    __syncthreads();

    const int lane = threadIdx.x & 31, w = threadIdx.x >> 5;
    const int warpId = blockIdx.x * (blockDim.x >> 5) + w;
    const int nWarps = gridDim.x * (blockDim.x >> 5);

    float2 bl = make_float2(blin[2 * lane], blin[2 * lane + 1]);
    float2 b1 = make_float2(ba1[2 * lane], ba1[2 * lane + 1]);

    for (int node = warpId; node < n; node += nWarps) {
        // zero agg for this node
        reinterpret_cast<float2*>(g_agg)[node * 32 + lane] = make_float2(0.f, 0.f);

        float2 hv = reinterpret_cast<const float2*>(h)[node * 32 + lane];
        float hsq = wredux(hv.x * hv.x + hv.y * hv.y);
        float nh = fmaxf(sqrtf(hsq), EPSV);
        float a = artanh_c(nh) * __fdividef(1.0f, nh);
        float2 lm = make_float2(hv.x * a, hv.y * a);

        // xt = lm @ Wlin.T  (shfl-broadcast GEMV)
        float2 acc = make_float2(0.f, 0.f);
#pragma unroll
        for (int s = 0; s < 32; ++s) {
            float xa = __shfl_sync(0xffffffffu, lm.x, s);
            float xb = __shfl_sync(0xffffffffu, lm.y, s);
            float2 w0 = sW[(2 * s) * 32 + lane];
            float2 w1 = sW[(2 * s + 1) * 32 + lane];
            acc.x = fmaf(w1.x, xb, fmaf(w0.x, xa, acc.x));
            acc.y = fmaf(w1.y, xb, fmaf(w0.y, xa, acc.y));
        }

        // res = expmap0(xt)
        float xsq = wredux(acc.x * acc.x + acc.y * acc.y);
        float nx = fmaxf(sqrtf(xsq), EPSV);
        float s0 = tanh_pos(nx) * __fdividef(1.0f, nx);
        float2 res = make_float2(acc.x * s0, acc.y * s0);
        float res2 = wredux(res.x * res.x + res.y * res.y);

        // hb = expmap(res, transp0(res, b)) : u = b*(1-res2)
        float omr = 1.0f - res2;
        float2 u = make_float2(bl.x * omr, bl.y * omr);
        float usq = wredux(u.x * u.x + u.y * u.y);
        float nu = fmaxf(sqrtf(usq), EPSV);
        float lam = 2.0f * __fdividef(1.0f, fmaxf(omr, EPSV));
        float ws = tanh_pos(0.5f * lam * nu) * __fdividef(1.0f, nu);
        float2 wv2 = make_float2(u.x * ws, u.y * ws);

        float y2 = wredux(wv2.x * wv2.x + wv2.y * wv2.y);
        float xy = wredux(res.x * wv2.x + res.y * wv2.y);
        float ca = 1.0f + 2.0f * xy + y2;
        float cb = 1.0f - res2;
        float den = fmaxf(1.0f + 2.0f * xy + res2 * y2, EPSV);
        float inv = __fdividef(1.0f, den);
        float2 hb = make_float2((ca * res.x + cb * wv2.x) * inv,
                                (ca * res.y + cb * wv2.y) * inv);

        float hbsq = wredux(hb.x * hb.x + hb.y * hb.y);
        g_hb[node * 32 + lane] = hb;
        if (lane == 0) g_nsq[node] = hbsq;

        float nb = fmaxf(sqrtf(hbsq), EPSV);
        float at = artanh_c(nb) * __fdividef(1.0f, nb);
        g_xtan[node * 32 + lane] = make_float2(hb.x * at, hb.y * at);

        // P = hb@A.T + ba1 ; Q = hb@B.T   (shfl-broadcast dual GEMV)
        float2 accP = b1;
        float2 accQ = make_float2(0.f, 0.f);
#pragma unroll
        for (int s = 0; s < 32; ++s) {
            float xa = __shfl_sync(0xffffffffu, hb.x, s);
            float xb = __shfl_sync(0xffffffffu, hb.y, s);
            float2 a0 = sA[(2 * s) * 32 + lane];
            float2 a1 = sA[(2 * s + 1) * 32 + lane];
            float2 q0 = sB[(2 * s) * 32 + lane];
            float2 q1 = sB[(2 * s + 1) * 32 + lane];
            accP.x = fmaf(a1.x, xb, fmaf(a0.x, xa, accP.x));
            accP.y = fmaf(a1.y, xb, fmaf(a0.y, xa, accP.y));
            accQ.x = fmaf(q1.x, xb, fmaf(q0.x, xa, accQ.x));
            accQ.y = fmaf(q1.y, xb, fmaf(q0.y, xa, accQ.y));
        }
        g_P[node * 32 + lane] = accP;
        g_Q[node * 32 + lane] = accQ;
    }
}

// =================== K2: edge attention + scatter (phased) ==================
template <bool FULL>
__device__ __forceinline__ void edge_chunk(
    int ch, int E, int lane,
    const int* __restrict__ edges, const float* __restrict__ dist,
    const float* __restrict__ emask,
    float2 wd, float2 wdd, float2 wa2, float b2s) {

    int e = ch * 32 + lane;
    bool valid = FULL || (e < E);
    int r = 0, c = 0;
    float dd = 0.f, em = 0.f, sr = 0.f, sc = 0.f;
    if (valid) {
        r = edges[e];
        c = edges[E + e];
        dd = dist[e];
        em = emask[e];
        sr = g_nsq[r];
        sc = g_nsq[c];
    }
    const int cnt = FULL ? 32 : (E - ch * 32);

    // ---- phase 1: per-edge dot xy (serial over chunk) ----
    float xyv = 0.f;
#pragma unroll 8
    for (int i = 0; i < (FULL ? 32 : cnt); ++i) {
        int ri = __shfl_sync(0xffffffffu, r, i);
        int ci = __shfl_sync(0xffffffffu, c, i);
        float2 hr = g_hb[ri * 32 + lane];
        float2 hc = g_hb[ci * 32 + lane];
        float xy = wredux(fmaf(hr.x, hc.x, hr.y * hc.y));
        if (lane == i) xyv = xy;
    }

    // ---- phase 2: hyperbolic distance, ALL 32 edges in parallel (1/lane) ----
    float al = 1.0f - 2.0f * xyv + sc;            // sc = y2
    float be = 1.0f - sr;                          // sr = x2
    float num2 = al * al * sr + be * be * sc - 2.0f * al * be * xyv;
    float den = fmaxf(1.0f - 2.0f * xyv + sr * sc, EPSV);
    float nrm = __fdividef(sqrtf(fmaxf(num2, 0.0f)), den);
    float dhv = 2.0f * artanh_c(nrm);

    // ---- phase 3: hidden layer + z reduction (serial over chunk) ----
    float zv = 0.f;
#pragma unroll 8
    for (int i = 0; i < (FULL ? 32 : cnt); ++i) {
        int ri   = __shfl_sync(0xffffffffu, r, i);
        int ci   = __shfl_sync(0xffffffffu, c, i);
        float dh = __shfl_sync(0xffffffffu, dhv, i);
        float di = __shfl_sync(0xffffffffu, dd, i);
        float2 p = g_P[ri * 32 + lane];
        float2 q = g_Q[ci * 32 + lane];
        float hx = fmaf(di, wdd.x, fmaf(dh, wd.x, p.x + q.x));
        float hy = fmaf(di, wdd.y, fmaf(dh, wd.y, p.y + q.y));
        float z = wredux(fmaf(siluf_(hx), wa2.x, siluf_(hy) * wa2.y));
        if (lane == i) zv = z;
    }

    // ---- phase 4: sigmoid for all 32 edges in parallel ----
    float scorev = sigmoidf_(zv + b2s) * em;

    // ---- phase 5: scatter (serial over chunk) ----
#pragma unroll 8
    for (int i = 0; i < (FULL ? 32 : cnt); ++i) {
        int ri  = __shfl_sync(0xffffffffu, r, i);
        int ci  = __shfl_sync(0xffffffffu, c, i);
        float s = __shfl_sync(0xffffffffu, scorev, i);
        float2 xc = g_xtan[ci * 32 + lane];
        red_add_v2(&g_agg[ri * 64 + 2 * lane], xc.x * s, xc.y * s);
    }
}

__global__ void __launch_bounds__(256)
k_edge(const int* __restrict__ edges,
       const float* __restrict__ dist,
       const float* __restrict__ emask,
       const float* __restrict__ Wa1,
       const float* __restrict__ Wa2,
       const float* __restrict__ ba2, int E) {
    const int lane = threadIdx.x & 31, w = threadIdx.x >> 5;

    float2 wd  = make_float2(Wa1[(2 * lane) * 130 + 128], Wa1[(2 * lane + 1) * 130 + 128]);
    float2 wdd = make_float2(Wa1[(2 * lane) * 130 + 129], Wa1[(2 * lane + 1) * 130 + 129]);
    float2 wa2 = make_float2(Wa2[2 * lane], Wa2[2 * lane + 1]);
    float  b2s = ba2[0];

    const int chunks = (E + 31) >> 5;
    const int fullChunks = E >> 5;
    const int c0 = blockIdx.x * (blockDim.x >> 5) + w;
    const int nch = gridDim.x * (blockDim.x >> 5);

    for (int ch = c0; ch < chunks; ch += nch) {
        if (ch < fullChunks)
            edge_chunk<true >(ch, E, lane, edges, dist, emask, wd, wdd, wa2, b2s);
        else
            edge_chunk<false>(ch, E, lane, edges, dist, emask, wd, wdd, wa2, b2s);
    }
}

// ========= K3: per-node MLP + expmap0/logmap0/silu epilogue =================
__global__ void __launch_bounds__(256)
k_node3(const float* __restrict__ Wm1,
        const float* __restrict__ bm1,
        const float* __restrict__ Wm2,
        const float* __restrict__ bm2,
        float* __restrict__ out, int n) {
    __shared__ float2 sW1[64 * 32];
    __shared__ float2 sW2[64 * 32];

    for (int idx = threadIdx.x; idx < 64 * 32; idx += blockDim.x) {
        int k = idx >> 5, t = idx & 31;
        sW1[idx] = make_float2(Wm1[(2 * t) * 64 + k], Wm1[(2 * t + 1) * 64 + k]);
        sW2[idx] = make_float2(Wm2[(2 * t) * 64 + k], Wm2[(2 * t + 1) * 64 + k]);
    }
    __syncthreads();

    const int lane = threadIdx.x & 31, w = threadIdx.x >> 5;
    const int warpId = blockIdx.x * (blockDim.x >> 5) + w;
    const int nWarps = gridDim.x * (blockDim.x >> 5);

    float2 b1 = make_float2(bm1[2 * lane], bm1[2 * lane + 1]);
    float2 b2 = make_float2(bm2[2 * lane], bm2[2 * lane + 1]);

    for (int node = warpId; node < n; node += nWarps) {
        float2 ag = reinterpret_cast<const float2*>(g_agg)[node * 32 + lane];
        ag.x *= 0.01f; ag.y *= 0.01f;

        float2 acc = b1;
#pragma unroll
        for (int s = 0; s < 32; ++s) {
            float xa = __shfl_sync(0xffffffffu, ag.x, s);
            float xb = __shfl_sync(0xffffffffu, ag.y, s);
            float2 w0 = sW1[(2 * s) * 32 + lane];
            float2 w1 = sW1[(2 * s + 1) * 32 + lane];
            acc.x = fmaf(w1.x, xb, fmaf(w0.x, xa, acc.x));
            acc.y = fmaf(w1.y, xb, fmaf(w0.y, xa, acc.y));
        }
        float2 hid = make_float2(siluf_(acc.x), siluf_(acc.y));

        float2 acc2 = b2;
#pragma unroll
        for (int s = 0; s < 32; ++s) {
            float xa = __shfl_sync(0xffffffffu, hid.x, s);
            float xb = __shfl_sync(0xffffffffu, hid.y, s);
            float2 w0 = sW2[(2 * s) * 32 + lane];
            float2 w1 = sW2[(2 * s + 1) * 32 + lane];
            acc2.x = fmaf(w1.x, xb, fmaf(w0.x, xa, acc2.x));
            acc2.y = fmaf(w1.y, xb, fmaf(w0.y, xa, acc2.y));
        }

        float2 xt = g_xtan[node * 32 + lane];
        float2 y = make_float2(xt.x + acc2.x, xt.y + acc2.y);

        // expmap0(y)
        float ysq = wredux(y.x * y.x + y.y * y.y);
        float ny = fmaxf(sqrtf(ysq), EPSV);
        float s1 = tanh_pos(ny) * __fdividef(1.0f, ny);
        float2 o1 = make_float2(y.x * s1, y.y * s1);

        // logmap0(o1)
        float osq = wredux(o1.x * o1.x + o1.y * o1.y);
        float no = fmaxf(sqrtf(osq), EPSV);
        float a2 = artanh_c(no) * __fdividef(1.0f, no);
        float2 t2 = make_float2(o1.x * a2, o1.y * a2);

        // silu
        float2 sl = make_float2(siluf_(t2.x), siluf_(t2.y));

        // expmap0
        float ssq = wredux(sl.x * sl.x + sl.y * sl.y);
        float ns = fmaxf(sqrtf(ssq), EPSV);
        float s3 = tanh_pos(ns) * __fdividef(1.0f, ns);

        reinterpret_cast<float2*>(out)[node * 32 + lane] =
            make_float2(sl.x * s3, sl.y * s3);
    }
}

// ------------------------------- launch -------------------------------------
extern "C" void kernel_launch(void* const* d_in, const int* in_sizes, int n_in,
                              void* d_out, int out_size) {
    const float* h         = (const float*)d_in[0];
    const float* distances = (const float*)d_in[1];
    const int*   edges     = (const int*)  d_in[2];
    // d_in[3] = node_mask (unused by reference)
    const float* edge_mask = (const float*)d_in[4];
    const float* W_lin     = (const float*)d_in[5];
    const float* b_lin     = (const float*)d_in[6];
    const float* Wa1       = (const float*)d_in[7];
    const float* ba1       = (const float*)d_in[8];
    const float* Wa2       = (const float*)d_in[9];
    const float* ba2       = (const float*)d_in[10];
    const float* Wm1       = (const float*)d_in[11];
    const float* bm1       = (const float*)d_in[12];
    const float* Wm2       = (const float*)d_in[13];
    const float* bm2       = (const float*)d_in[14];

    int N = in_sizes[0] / 64;
    int E = in_sizes[1];

    k_nodeA<<<512, 256>>>(h, W_lin, b_lin, Wa1, ba1, N);
    k_edge<<<2048, 256>>>(edges, distances, edge_mask, Wa1, Wa2, ba2, E);
    k_node3<<<512, 256>>>(Wm1, bm1, Wm2, bm2, (float*)d_out, N);
}

// round 4
// speedup vs baseline: 1.3504x; 1.2050x over previous
#include <cuda_runtime.h>
#include <cuda_bf16.h>

#define EPSV 1e-7f
#define MAXN 50000

// ------------------------- static device scratch ---------------------------
__device__ __align__(16) float2 g_hb  [MAXN * 32];
__device__ __align__(16) float2 g_xtan[MAXN * 32];
__device__ __align__(16) float2 g_P   [MAXN * 32];   // hb@A.T + ba1 (bias folded)
__device__ __align__(16) float2 g_Q   [MAXN * 32];   // hb@B.T
__device__ __align__(16) float  g_nsq [MAXN];
__device__ __align__(16) float  g_agg [MAXN * 64];

// ------------------------------ helpers ------------------------------------
__device__ __forceinline__ float wredux(float v) {
    v += __shfl_xor_sync(0xffffffffu, v, 16);
    v += __shfl_xor_sync(0xffffffffu, v, 8);
    v += __shfl_xor_sync(0xffffffffu, v, 4);
    v += __shfl_xor_sync(0xffffffffu, v, 2);
    v += __shfl_xor_sync(0xffffffffu, v, 1);
    return v;
}

__device__ __forceinline__ void red_add_v2(float* addr, float a, float b) {
    asm volatile("red.global.add.v2.f32 [%0], {%1, %2};"
                 :: "l"(addr), "f"(a), "f"(b) : "memory");
}

__device__ __forceinline__ float artanh_c(float x) {
    x = fminf(x, 1.0f - EPSV);
    return 0.5f * __logf(__fdividef(1.0f + x, 1.0f - x));
}

__device__ __forceinline__ float tanh_pos(float x) {  // x >= 0
    float e = __expf(-2.0f * x);
    return (1.0f - e) * __fdividef(1.0f, 1.0f + e);
}

__device__ __forceinline__ float sigmoidf_(float z) {
    return __fdividef(1.0f, 1.0f + __expf(-z));
}

__device__ __forceinline__ float siluf_(float z) {
    return z * sigmoidf_(z);
}

// ===== K1 (fused, 4-node batched): HypLinear -> hb,nsq,xtan,P,Q, zero agg ===
__global__ void __launch_bounds__(256)
k_nodeA(const float* __restrict__ h,
        const float* __restrict__ Wlin,
        const float* __restrict__ blin,
        const float* __restrict__ Wa1,
        const float* __restrict__ ba1, int n) {
    // step s, lane t: {W[2t][2s], W[2t+1][2s], W[2t][2s+1], W[2t+1][2s+1]}
    __shared__ float4 sW4[32 * 32];
    __shared__ float4 sA4[32 * 32];
    __shared__ float4 sB4[32 * 32];

    for (int idx = threadIdx.x; idx < 32 * 32; idx += blockDim.x) {
        int s = idx >> 5, t = idx & 31;
        sW4[idx] = make_float4(Wlin[(2 * t) * 64 + 2 * s],     Wlin[(2 * t + 1) * 64 + 2 * s],
                               Wlin[(2 * t) * 64 + 2 * s + 1], Wlin[(2 * t + 1) * 64 + 2 * s + 1]);
        sA4[idx] = make_float4(Wa1[(2 * t) * 130 + 2 * s],     Wa1[(2 * t + 1) * 130 + 2 * s],
                               Wa1[(2 * t) * 130 + 2 * s + 1], Wa1[(2 * t + 1) * 130 + 2 * s + 1]);
        sB4[idx] = make_float4(Wa1[(2 * t) * 130 + 64 + 2 * s],     Wa1[(2 * t + 1) * 130 + 64 + 2 * s],
                               Wa1[(2 * t) * 130 + 64 + 2 * s + 1], Wa1[(2 * t + 1) * 130 + 64 + 2 * s + 1]);
    }
    __syncthreads();

    const int lane = threadIdx.x & 31, w = threadIdx.x >> 5;
    const int warpId = blockIdx.x * (blockDim.x >> 5) + w;
    const int nWarps = gridDim.x * (blockDim.x >> 5);

    float2 bl = make_float2(blin[2 * lane], blin[2 * lane + 1]);
    float2 b1 = make_float2(ba1[2 * lane], ba1[2 * lane + 1]);
    const float bsq = wredux(bl.x * bl.x + bl.y * bl.y);   // hoisted (constant)

    for (int base = warpId * 4; base < n; base += nWarps * 4) {
        int  nd[4]; bool val[4];
#pragma unroll
        for (int j = 0; j < 4; ++j) {
            int node = base + j;
            val[j] = (node < n);
            nd[j] = val[j] ? node : base;
        }

        float2 hv[4];
#pragma unroll
        for (int j = 0; j < 4; ++j) {
            hv[j] = reinterpret_cast<const float2*>(h)[nd[j] * 32 + lane];
            if (val[j])
                reinterpret_cast<float2*>(g_agg)[nd[j] * 32 + lane] = make_float2(0.f, 0.f);
        }

        float2 lm[4];
#pragma unroll
        for (int j = 0; j < 4; ++j) {
            float hsq = wredux(hv[j].x * hv[j].x + hv[j].y * hv[j].y);
            float nh = fmaxf(sqrtf(hsq), EPSV);
            float a = artanh_c(nh) * __fdividef(1.0f, nh);
            lm[j] = make_float2(hv[j].x * a, hv[j].y * a);
        }

        // GEMV1: acc = lm @ Wlin.T  (weights shared across 4 nodes)
        float2 acc[4] = {{0.f,0.f},{0.f,0.f},{0.f,0.f},{0.f,0.f}};
#pragma unroll
        for (int s = 0; s < 32; ++s) {
            float4 w4 = sW4[s * 32 + lane];
#pragma unroll
            for (int j = 0; j < 4; ++j) {
                float xa = __shfl_sync(0xffffffffu, lm[j].x, s);
                float xb = __shfl_sync(0xffffffffu, lm[j].y, s);
                acc[j].x = fmaf(w4.x, xa, fmaf(w4.z, xb, acc[j].x));
                acc[j].y = fmaf(w4.y, xa, fmaf(w4.w, xb, acc[j].y));
            }
        }

        float2 hb[4];
#pragma unroll
        for (int j = 0; j < 4; ++j) {
            float xsq = wredux(acc[j].x * acc[j].x + acc[j].y * acc[j].y);
            float nx = fmaxf(sqrtf(xsq), EPSV);
            float s0 = tanh_pos(nx) * __fdividef(1.0f, nx);
            float2 res = make_float2(acc[j].x * s0, acc[j].y * s0);
            float res2 = xsq * s0 * s0;

            float omr = 1.0f - res2;
            float usq = bsq * omr * omr;
            float nu = fmaxf(sqrtf(usq), EPSV);
            float lam = 2.0f * __fdividef(1.0f, fmaxf(omr, EPSV));
            float ws = tanh_pos(0.5f * lam * nu) * __fdividef(1.0f, nu);
            float2 wv2 = make_float2(bl.x * (omr * ws), bl.y * (omr * ws));

            float y2 = usq * ws * ws;
            float rb = wredux(res.x * bl.x + res.y * bl.y);
            float xy = ws * omr * rb;

            float ca = 1.0f + 2.0f * xy + y2;
            float den = fmaxf(1.0f + 2.0f * xy + res2 * y2, EPSV);
            float inv = __fdividef(1.0f, den);
            hb[j] = make_float2((ca * res.x + omr * wv2.x) * inv,
                                (ca * res.y + omr * wv2.y) * inv);

            float hbsq = wredux(hb[j].x * hb[j].x + hb[j].y * hb[j].y);
            float nb = fmaxf(sqrtf(hbsq), EPSV);
            float at = artanh_c(nb) * __fdividef(1.0f, nb);
            if (val[j]) {
                g_hb[nd[j] * 32 + lane] = hb[j];
                if (lane == 0) g_nsq[nd[j]] = hbsq;
                g_xtan[nd[j] * 32 + lane] = make_float2(hb[j].x * at, hb[j].y * at);
            }
        }

        // Dual GEMV: P = hb@A.T + ba1 ; Q = hb@B.T
        float2 aP[4] = {b1, b1, b1, b1};
        float2 aQ[4] = {{0.f,0.f},{0.f,0.f},{0.f,0.f},{0.f,0.f}};
#pragma unroll
        for (int s = 0; s < 32; ++s) {
            float4 a4 = sA4[s * 32 + lane];
            float4 q4 = sB4[s * 32 + lane];
#pragma unroll
            for (int j = 0; j < 4; ++j) {
                float xa = __shfl_sync(0xffffffffu, hb[j].x, s);
                float xb = __shfl_sync(0xffffffffu, hb[j].y, s);
                aP[j].x = fmaf(a4.x, xa, fmaf(a4.z, xb, aP[j].x));
                aP[j].y = fmaf(a4.y, xa, fmaf(a4.w, xb, aP[j].y));
                aQ[j].x = fmaf(q4.x, xa, fmaf(q4.z, xb, aQ[j].x));
                aQ[j].y = fmaf(q4.y, xa, fmaf(q4.w, xb, aQ[j].y));
            }
        }
#pragma unroll
        for (int j = 0; j < 4; ++j) {
            if (val[j]) {
                g_P[nd[j] * 32 + lane] = aP[j];
                g_Q[nd[j] * 32 + lane] = aQ[j];
            }
        }
    }
}

// =================== K2: edge attention + scatter (phased) ==================
template <bool FULL>
__device__ __forceinline__ void edge_chunk(
    int ch, int E, int lane, int w,
    const int* __restrict__ edges, const float* __restrict__ dist,
    const float* __restrict__ emask,
    float2 wd, float2 wdd, float2 wa2, float b2s,
    int2 (*s_rc)[32], float2 (*s_dx)[32], float (*s_sc)[32]) {

    int e = ch * 32 + lane;
    bool valid = FULL || (e < E);
    int r = 0, c = 0;
    float dd = 0.f, em = 0.f, sr = 0.f, sc = 0.f;
    if (valid) {
        r = edges[e];
        c = edges[E + e];
        dd = dist[e];
        em = emask[e];
        sr = g_nsq[r];
        sc = g_nsq[c];
    }
    const int cnt = FULL ? 32 : (E - ch * 32);

    __syncwarp();                       // WAR: prev chunk's reads done
    s_rc[w][lane] = make_int2(r * 32, c * 32);
    __syncwarp();

    // ---- phase 1: per-edge dot xy (serial over chunk) ----
    float xyv = 0.f;
#pragma unroll 8
    for (int i = 0; i < (FULL ? 32 : cnt); ++i) {
        int2 rc = s_rc[w][i];
        float2 hr = g_hb[rc.x + lane];
        float2 hc = g_hb[rc.y + lane];
        float xy = wredux(fmaf(hr.x, hc.x, hr.y * hc.y));
        if (lane == i) xyv = xy;
    }

    // ---- phase 2: hyperbolic distance, all 32 edges in parallel ----
    float al = 1.0f - 2.0f * xyv + sc;            // sc = y2
    float be = 1.0f - sr;                          // sr = x2
    float num2 = al * al * sr + be * be * sc - 2.0f * al * be * xyv;
    float den = fmaxf(1.0f - 2.0f * xyv + sr * sc, EPSV);
    float nrm = __fdividef(sqrtf(fmaxf(num2, 0.0f)), den);
    float dhv = 2.0f * artanh_c(nrm);

    s_dx[w][lane] = make_float2(dhv, dd);
    __syncwarp();

    // ---- phase 3: hidden layer + z reduction (serial over chunk) ----
    float zv = 0.f;
#pragma unroll 8
    for (int i = 0; i < (FULL ? 32 : cnt); ++i) {
        int2 rc = s_rc[w][i];
        float2 dx = s_dx[w][i];
        float2 p = g_P[rc.x + lane];
        float2 q = g_Q[rc.y + lane];
        float hx = fmaf(dx.y, wdd.x, fmaf(dx.x, wd.x, p.x + q.x));
        float hy = fmaf(dx.y, wdd.y, fmaf(dx.x, wd.y, p.y + q.y));
        float z = wredux(fmaf(siluf_(hx), wa2.x, siluf_(hy) * wa2.y));
        if (lane == i) zv = z;
    }

    // ---- phase 4: sigmoid, all 32 edges in parallel ----
    float scorev = sigmoidf_(zv + b2s) * em;
    s_sc[w][lane] = scorev;
    __syncwarp();

    // ---- phase 5: scatter (serial over chunk) ----
#pragma unroll 8
    for (int i = 0; i < (FULL ? 32 : cnt); ++i) {
        int2 rc = s_rc[w][i];
        float s = s_sc[w][i];
        float2 xc = g_xtan[rc.y + lane];
        red_add_v2(&g_agg[rc.x * 2 + 2 * lane], xc.x * s, xc.y * s);
    }
}

__global__ void __launch_bounds__(256)
k_edge(const int* __restrict__ edges,
       const float* __restrict__ dist,
       const float* __restrict__ emask,
       const float* __restrict__ Wa1,
       const float* __restrict__ Wa2,
       const float* __restrict__ ba2, int E) {
    __shared__ int2   s_rc[8][32];
    __shared__ float2 s_dx[8][32];
    __shared__ float  s_sc[8][32];

    const int lane = threadIdx.x & 31, w = threadIdx.x >> 5;

    float2 wd  = make_float2(Wa1[(2 * lane) * 130 + 128], Wa1[(2 * lane + 1) * 130 + 128]);
    float2 wdd = make_float2(Wa1[(2 * lane) * 130 + 129], Wa1[(2 * lane + 1) * 130 + 129]);
    float2 wa2 = make_float2(Wa2[2 * lane], Wa2[2 * lane + 1]);
    float  b2s = ba2[0];

    const int chunks = (E + 31) >> 5;
    const int fullChunks = E >> 5;
    const int c0 = blockIdx.x * (blockDim.x >> 5) + w;
    const int nch = gridDim.x * (blockDim.x >> 5);

    for (int ch = c0; ch < chunks; ch += nch) {
        if (ch < fullChunks)
            edge_chunk<true >(ch, E, lane, w, edges, dist, emask, wd, wdd, wa2, b2s,
                              s_rc, s_dx, s_sc);
        else
            edge_chunk<false>(ch, E, lane, w, edges, dist, emask, wd, wdd, wa2, b2s,
                              s_rc, s_dx, s_sc);
    }
}

// ===== K3 (4-node batched): MLP + expmap0/logmap0/silu epilogue =============
__global__ void __launch_bounds__(256)
k_node3(const float* __restrict__ Wm1,
        const float* __restrict__ bm1,
        const float* __restrict__ Wm2,
        const float* __restrict__ bm2,
        float* __restrict__ out, int n) {
    __shared__ float4 sW1[32 * 32];
    __shared__ float4 sW2[32 * 32];

    for (int idx = threadIdx.x; idx < 32 * 32; idx += blockDim.x) {
        int s = idx >> 5, t = idx & 31;
        sW1[idx] = make_float4(Wm1[(2 * t) * 64 + 2 * s],     Wm1[(2 * t + 1) * 64 + 2 * s],
                               Wm1[(2 * t) * 64 + 2 * s + 1], Wm1[(2 * t + 1) * 64 + 2 * s + 1]);
        sW2[idx] = make_float4(Wm2[(2 * t) * 64 + 2 * s],     Wm2[(2 * t + 1) * 64 + 2 * s],
                               Wm2[(2 * t) * 64 + 2 * s + 1], Wm2[(2 * t + 1) * 64 + 2 * s + 1]);
    }
    __syncthreads();

    const int lane = threadIdx.x & 31, w = threadIdx.x >> 5;
    const int warpId = blockIdx.x * (blockDim.x >> 5) + w;
    const int nWarps = gridDim.x * (blockDim.x >> 5);

    float2 b1 = make_float2(bm1[2 * lane], bm1[2 * lane + 1]);
    float2 b2 = make_float2(bm2[2 * lane], bm2[2 * lane + 1]);

    for (int base = warpId * 4; base < n; base += nWarps * 4) {
        int  nd[4]; bool val[4];
#pragma unroll
        for (int j = 0; j < 4; ++j) {
            int node = base + j;
            val[j] = (node < n);
            nd[j] = val[j] ? node : base;
        }

        float2 ag[4];
#pragma unroll
        for (int j = 0; j < 4; ++j) {
            ag[j] = reinterpret_cast<const float2*>(g_agg)[nd[j] * 32 + lane];
            ag[j].x *= 0.01f; ag[j].y *= 0.01f;
        }

        float2 acc[4] = {b1, b1, b1, b1};
#pragma unroll
        for (int s = 0; s < 32; ++s) {
            float4 w4 = sW1[s * 32 + lane];
#pragma unroll
            for (int j = 0; j < 4; ++j) {
                float xa = __shfl_sync(0xffffffffu, ag[j].x, s);
                float xb = __shfl_sync(0xffffffffu, ag[j].y, s);
                acc[j].x = fmaf(w4.x, xa, fmaf(w4.z, xb, acc[j].x));
                acc[j].y = fmaf(w4.y, xa, fmaf(w4.w, xb, acc[j].y));
            }
        }

        float2 hid[4];
#pragma unroll
        for (int j = 0; j < 4; ++j)
            hid[j] = make_float2(siluf_(acc[j].x), siluf_(acc[j].y));

        float2 acc2[4] = {b2, b2, b2, b2};
#pragma unroll
        for (int s = 0; s < 32; ++s) {
            float4 w4 = sW2[s * 32 + lane];
#pragma unroll
            for (int j = 0; j < 4; ++j) {
                float xa = __shfl_sync(0xffffffffu, hid[j].x, s);
                float xb = __shfl_sync(0xffffffffu, hid[j].y, s);
                acc2[j].x = fmaf(w4.x, xa, fmaf(w4.z, xb, acc2[j].x));
                acc2[j].y = fmaf(w4.y, xa, fmaf(w4.w, xb, acc2[j].y));
            }
        }

#pragma unroll
        for (int j = 0; j < 4; ++j) {
            float2 xt = g_xtan[nd[j] * 32 + lane];
            float2 y = make_float2(xt.x + acc2[j].x, xt.y + acc2[j].y);

            // expmap0(y)
            float ysq = wredux(y.x * y.x + y.y * y.y);
            float ny = fmaxf(sqrtf(ysq), EPSV);
            float t = tanh_pos(ny);
            float s1 = t * __fdividef(1.0f, ny);
            float2 o1 = make_float2(y.x * s1, y.y * s1);

            // logmap0(o1): ||o1|| == tanh(ny) analytically
            float no = fmaxf(t, EPSV);
            float a2 = artanh_c(no) * __fdividef(1.0f, no);
            float2 t2 = make_float2(o1.x * a2, o1.y * a2);

            // silu
            float2 sl = make_float2(siluf_(t2.x), siluf_(t2.y));

            // expmap0
            float ssq = wredux(sl.x * sl.x + sl.y * sl.y);
            float ns = fmaxf(sqrtf(ssq), EPSV);
            float s3 = tanh_pos(ns) * __fdividef(1.0f, ns);

            if (val[j])
                reinterpret_cast<float2*>(out)[nd[j] * 32 + lane] =
                    make_float2(sl.x * s3, sl.y * s3);
        }
    }
}

// ------------------------------- launch -------------------------------------
extern "C" void kernel_launch(void* const* d_in, const int* in_sizes, int n_in,
                              void* d_out, int out_size) {
    const float* h         = (const float*)d_in[0];
    const float* distances = (const float*)d_in[1];
    const int*   edges     = (const int*)  d_in[2];
    // d_in[3] = node_mask (unused by reference)
    const float* edge_mask = (const float*)d_in[4];
    const float* W_lin     = (const float*)d_in[5];
    const float* b_lin     = (const float*)d_in[6];
    const float* Wa1       = (const float*)d_in[7];
    const float* ba1       = (const float*)d_in[8];
    const float* Wa2       = (const float*)d_in[9];
    const float* ba2       = (const float*)d_in[10];
    const float* Wm1       = (const float*)d_in[11];
    const float* bm1       = (const float*)d_in[12];
    const float* Wm2       = (const float*)d_in[13];
    const float* bm2       = (const float*)d_in[14];

    int N = in_sizes[0] / 64;
    int E = in_sizes[1];

    int warpsNeeded = (N + 3) / 4;                 // 4 nodes per warp
    int blocksA = (warpsNeeded + 7) / 8;           // 8 warps per block

    k_nodeA<<<blocksA, 256>>>(h, W_lin, b_lin, Wa1, ba1, N);
    k_edge<<<2048, 256>>>(edges, distances, edge_mask, Wa1, Wa2, ba2, E);
    k_node3<<<blocksA, 256>>>(Wm1, bm1, Wm2, bm2, (float*)d_out, N);
}

// round 5
// speedup vs baseline: 1.6839x; 1.2470x over previous
#include <cuda_runtime.h>
#include <cuda_bf16.h>

#define EPSV 1e-7f
#define MAXN 50000

// ------------------------- static device scratch ---------------------------
__device__ __align__(16) float4 g_hb4[MAXN * 16];
__device__ __align__(16) float4 g_xt4[MAXN * 16];
__device__ __align__(16) float4 g_P4 [MAXN * 16];   // hb@A.T + ba1
__device__ __align__(16) float4 g_Q4 [MAXN * 16];   // hb@B.T
__device__ float g_nsq[MAXN];
__device__ __align__(16) float g_agg[MAXN * 64];

// ------------------------------ helpers ------------------------------------
__device__ __forceinline__ float artanh_c(float x) {
    x = fminf(x, 1.0f - EPSV);
    return 0.5f * __logf(__fdividef(1.0f + x, 1.0f - x));
}
__device__ __forceinline__ float tanh_pos(float x) {  // x >= 0
    float e = __expf(-2.0f * x);
    return (1.0f - e) * __fdividef(1.0f, 1.0f + e);
}
__device__ __forceinline__ float sigmoidf_(float z) {
    return __fdividef(1.0f, 1.0f + __expf(-z));
}
__device__ __forceinline__ float siluf_(float z) {
    return z * sigmoidf_(z);
}
__device__ __forceinline__ void red_add_v4(float* a, float x, float y, float z, float w) {
    asm volatile("red.global.add.v4.f32 [%0], {%1, %2, %3, %4};"
                 :: "l"(a), "f"(x), "f"(y), "f"(z), "f"(w) : "memory");
}

#define WSTRIDE 68   // transposed weight row stride (floats): 16B-aligned, banks spread

// ===== K1 (thread-per-node): HypLinear -> hb, nsq, xtan, P, Q, zero agg =====
__global__ void __launch_bounds__(128)
k_nodeA(const float* __restrict__ h,
        const float* __restrict__ Wlin,
        const float* __restrict__ blin,
        const float* __restrict__ Wa1,
        const float* __restrict__ ba1, int n) {
    extern __shared__ float sm[];
    float* sWt = sm;                      // [64][WSTRIDE]: sWt[k*WS+o] = Wlin[o][k]
    float* sAt = sm + 64 * WSTRIDE;       // Wa1[:,0:64]^T
    float* sBt = sm + 2 * 64 * WSTRIDE;   // Wa1[:,64:128]^T
    float* sbl = sm + 3 * 64 * WSTRIDE;   // blin
    float* sb1 = sbl + 64;                // ba1

    const int tid = threadIdx.x;
    for (int idx = tid; idx < 4096; idx += 128) {
        int o = idx >> 6, k = idx & 63;
        sWt[k * WSTRIDE + o] = Wlin[idx];
    }
    for (int idx = tid; idx < 8192; idx += 128) {
        int half = idx >> 12, o = (idx >> 6) & 63, k = idx & 63;
        float v = Wa1[o * 130 + half * 64 + k];
        (half ? sBt : sAt)[k * WSTRIDE + o] = v;
    }
    if (tid < 64) { sbl[tid] = blin[tid]; sb1[tid] = ba1[tid]; }
    __syncthreads();

    int node = blockIdx.x * 128 + tid;
    bool valid = node < n;
    int nd = valid ? node : 0;

    // load h, compute ||h||^2
    const float4* hp = reinterpret_cast<const float4*>(h) + (size_t)nd * 16;
    float4 hv[16];
    float hsq = 0.f;
#pragma unroll
    for (int i = 0; i < 16; ++i) {
        hv[i] = hp[i];
        hsq += hv[i].x * hv[i].x + hv[i].y * hv[i].y + hv[i].z * hv[i].z + hv[i].w * hv[i].w;
    }
    float nh = fmaxf(sqrtf(hsq), EPSV);
    float a = artanh_c(nh) * __fdividef(1.0f, nh);

    // stage lm = a*h into local (dynamic-k indexable)
    float xloc[64];
#pragma unroll
    for (int i = 0; i < 16; ++i) {
        xloc[4 * i + 0] = hv[i].x * a;
        xloc[4 * i + 1] = hv[i].y * a;
        xloc[4 * i + 2] = hv[i].z * a;
        xloc[4 * i + 3] = hv[i].w * a;
    }

    // GEMV1: acc = lm @ Wlin.T (uniform broadcast weights)
    float4 acc[16];
#pragma unroll
    for (int i = 0; i < 16; ++i) acc[i] = make_float4(0.f, 0.f, 0.f, 0.f);
#pragma unroll 4
    for (int k = 0; k < 64; ++k) {
        float xk = xloc[k];
        const float4* wr = reinterpret_cast<const float4*>(sWt + k * WSTRIDE);
#pragma unroll
        for (int j = 0; j < 16; ++j) {
            float4 w4 = wr[j];
            acc[j].x = fmaf(w4.x, xk, acc[j].x);
            acc[j].y = fmaf(w4.y, xk, acc[j].y);
            acc[j].z = fmaf(w4.z, xk, acc[j].z);
            acc[j].w = fmaf(w4.w, xk, acc[j].w);
        }
    }

    // res = expmap0(acc); per-thread scalar math (no reductions!)
    float xsq = 0.f;
#pragma unroll
    for (int i = 0; i < 16; ++i)
        xsq += acc[i].x * acc[i].x + acc[i].y * acc[i].y + acc[i].z * acc[i].z + acc[i].w * acc[i].w;
    float nx = fmaxf(sqrtf(xsq), EPSV);
    float s0 = tanh_pos(nx) * __fdividef(1.0f, nx);
    float res2 = xsq * s0 * s0;
    float omr = 1.0f - res2;

    float bsq = 0.f, rb = 0.f;
#pragma unroll
    for (int i = 0; i < 16; ++i) {
        float4 b4 = *reinterpret_cast<const float4*>(sbl + 4 * i);
        bsq += b4.x * b4.x + b4.y * b4.y + b4.z * b4.z + b4.w * b4.w;
        rb  += acc[i].x * b4.x + acc[i].y * b4.y + acc[i].z * b4.z + acc[i].w * b4.w;
    }
    rb *= s0;   // res . b

    float usq = bsq * omr * omr;
    float nu = fmaxf(sqrtf(usq), EPSV);
    float lam = 2.0f * __fdividef(1.0f, fmaxf(omr, EPSV));
    float ws = tanh_pos(0.5f * lam * nu) * __fdividef(1.0f, nu);
    float y2 = usq * ws * ws;
    float xy = ws * omr * rb;
    float ca = 1.0f + 2.0f * xy + y2;
    float den = fmaxf(1.0f + 2.0f * xy + res2 * y2, EPSV);
    float inv = __fdividef(1.0f, den);
    float c1 = ca * s0 * inv;            // multiplies raw acc (res = s0*acc)
    float c2 = omr * omr * ws * inv;     // multiplies b

    // hb into acc (overwrite), write g_hb, stage hloc
    float hloc[64];
    float hbsq = 0.f;
    float4* ghb = g_hb4 + (size_t)nd * 16;
#pragma unroll
    for (int i = 0; i < 16; ++i) {
        float4 b4 = *reinterpret_cast<const float4*>(sbl + 4 * i);
        float4 hb;
        hb.x = c1 * acc[i].x + c2 * b4.x;
        hb.y = c1 * acc[i].y + c2 * b4.y;
        hb.z = c1 * acc[i].z + c2 * b4.z;
        hb.w = c1 * acc[i].w + c2 * b4.w;
        hbsq += hb.x * hb.x + hb.y * hb.y + hb.z * hb.z + hb.w * hb.w;
        hloc[4 * i + 0] = hb.x; hloc[4 * i + 1] = hb.y;
        hloc[4 * i + 2] = hb.z; hloc[4 * i + 3] = hb.w;
        acc[i] = hb;
        if (valid) ghb[i] = hb;
    }
    if (valid) g_nsq[nd] = hbsq;

    float nb = fmaxf(sqrtf(hbsq), EPSV);
    float at = artanh_c(nb) * __fdividef(1.0f, nb);
    float4* gxt = g_xt4 + (size_t)nd * 16;
    float4* gag = reinterpret_cast<float4*>(g_agg) + (size_t)nd * 16;
#pragma unroll
    for (int i = 0; i < 16; ++i) {
        if (valid) {
            gxt[i] = make_float4(acc[i].x * at, acc[i].y * at, acc[i].z * at, acc[i].w * at);
            gag[i] = make_float4(0.f, 0.f, 0.f, 0.f);
        }
    }

    // GEMV P = hb@A.T + ba1
    float4 accP[16];
#pragma unroll
    for (int i = 0; i < 16; ++i) accP[i] = make_float4(0.f, 0.f, 0.f, 0.f);
#pragma unroll 4
    for (int k = 0; k < 64; ++k) {
        float hk = hloc[k];
        const float4* wr = reinterpret_cast<const float4*>(sAt + k * WSTRIDE);
#pragma unroll
        for (int j = 0; j < 16; ++j) {
            float4 w4 = wr[j];
            accP[j].x = fmaf(w4.x, hk, accP[j].x);
            accP[j].y = fmaf(w4.y, hk, accP[j].y);
            accP[j].z = fmaf(w4.z, hk, accP[j].z);
            accP[j].w = fmaf(w4.w, hk, accP[j].w);
        }
    }
    float4* gP = g_P4 + (size_t)nd * 16;
#pragma unroll
    for (int i = 0; i < 16; ++i) {
        float4 b4 = *reinterpret_cast<const float4*>(sb1 + 4 * i);
        if (valid)
            gP[i] = make_float4(accP[i].x + b4.x, accP[i].y + b4.y,
                                accP[i].z + b4.z, accP[i].w + b4.w);
    }

    // GEMV Q = hb@B.T
#pragma unroll
    for (int i = 0; i < 16; ++i) accP[i] = make_float4(0.f, 0.f, 0.f, 0.f);
#pragma unroll 4
    for (int k = 0; k < 64; ++k) {
        float hk = hloc[k];
        const float4* wr = reinterpret_cast<const float4*>(sBt + k * WSTRIDE);
#pragma unroll
        for (int j = 0; j < 16; ++j) {
            float4 w4 = wr[j];
            accP[j].x = fmaf(w4.x, hk, accP[j].x);
            accP[j].y = fmaf(w4.y, hk, accP[j].y);
            accP[j].z = fmaf(w4.z, hk, accP[j].z);
            accP[j].w = fmaf(w4.w, hk, accP[j].w);
        }
    }
    float4* gQ = g_Q4 + (size_t)nd * 16;
#pragma unroll
    for (int i = 0; i < 16; ++i)
        if (valid) gQ[i] = accP[i];
}

// ========== K2: edge attention + scatter (16 lanes/edge, float4) ============
__global__ void __launch_bounds__(256)
k_edge(const int* __restrict__ edges,
       const float* __restrict__ dist,
       const float* __restrict__ emask,
       const float* __restrict__ Wa1,
       const float* __restrict__ Wa2,
       const float* __restrict__ ba2, int E) {
    __shared__ int   s_r [8][32];
    __shared__ int   s_c [8][32];
    __shared__ float s_xy[8][32];
    __shared__ float s_dh[8][32];
    __shared__ float s_dd[8][32];
    __shared__ float s_sc[8][32];

    const int lane = threadIdx.x & 31, w = threadIdx.x >> 5;
    const int g = lane >> 4, l16 = lane & 15;
    const unsigned FM = 0xffffffffu;

    float4 wd4  = make_float4(Wa1[(4 * l16 + 0) * 130 + 128], Wa1[(4 * l16 + 1) * 130 + 128],
                              Wa1[(4 * l16 + 2) * 130 + 128], Wa1[(4 * l16 + 3) * 130 + 128]);
    float4 wdd4 = make_float4(Wa1[(4 * l16 + 0) * 130 + 129], Wa1[(4 * l16 + 1) * 130 + 129],
                              Wa1[(4 * l16 + 2) * 130 + 129], Wa1[(4 * l16 + 3) * 130 + 129]);
    float4 wa24 = make_float4(Wa2[4 * l16 + 0], Wa2[4 * l16 + 1],
                              Wa2[4 * l16 + 2], Wa2[4 * l16 + 3]);
    float b2s = ba2[0];

    const int chunks = (E + 31) >> 5;
    for (int ch = blockIdx.x * 8 + w; ch < chunks; ch += gridDim.x * 8) {
        int e = ch * 32 + lane;
        bool v = e < E;
        int r = 0, c = 0;
        float dd = 0.f, em = 0.f, sr = 0.f, sc_ = 0.f;
        if (v) {
            r = edges[e];
            c = edges[E + e];
            dd = dist[e];
            em = emask[e];
            sr = g_nsq[r];
            sc_ = g_nsq[c];
        }
        __syncwarp();                 // prior chunk reads done
        s_r[w][lane] = r; s_c[w][lane] = c; s_dd[w][lane] = dd;
        __syncwarp();

        // ---- phase 1: per-edge dot xy (2 edges per iteration) ----
#pragma unroll 4
        for (int i = 0; i < 16; ++i) {
            int er = s_r[w][2 * i + g], ec = s_c[w][2 * i + g];
            float4 hr = g_hb4[er * 16 + l16];
            float4 hc = g_hb4[ec * 16 + l16];
            float d = hr.x * hc.x + hr.y * hc.y + hr.z * hc.z + hr.w * hc.w;
            d += __shfl_xor_sync(FM, d, 8);
            d += __shfl_xor_sync(FM, d, 4);
            d += __shfl_xor_sync(FM, d, 2);
            d += __shfl_xor_sync(FM, d, 1);
            if (l16 == 0) s_xy[w][2 * i + g] = d;
        }
        __syncwarp();

        // ---- phase 2: hyperbolic distance (lane = edge, parallel) ----
        {
            float xyv = s_xy[w][lane];
            float al = 1.0f - 2.0f * xyv + sc_;
            float be = 1.0f - sr;
            float num2 = al * al * sr + be * be * sc_ - 2.0f * al * be * xyv;
            float den = fmaxf(1.0f - 2.0f * xyv + sr * sc_, EPSV);
            float nrm = __fdividef(sqrtf(fmaxf(num2, 0.0f)), den);
            s_dh[w][lane] = 2.0f * artanh_c(nrm);
        }
        __syncwarp();

        // ---- phase 3: hidden layer + z ----
#pragma unroll 4
        for (int i = 0; i < 16; ++i) {
            int er = s_r[w][2 * i + g], ec = s_c[w][2 * i + g];
            float dh = s_dh[w][2 * i + g], di = s_dd[w][2 * i + g];
            float4 p = g_P4[er * 16 + l16];
            float4 q = g_Q4[ec * 16 + l16];
            float hx = fmaf(di, wdd4.x, fmaf(dh, wd4.x, p.x + q.x));
            float hy = fmaf(di, wdd4.y, fmaf(dh, wd4.y, p.y + q.y));
            float hz = fmaf(di, wdd4.z, fmaf(dh, wd4.z, p.z + q.z));
            float hw = fmaf(di, wdd4.w, fmaf(dh, wd4.w, p.w + q.w));
            float z = siluf_(hx) * wa24.x;
            z = fmaf(siluf_(hy), wa24.y, z);
            z = fmaf(siluf_(hz), wa24.z, z);
            z = fmaf(siluf_(hw), wa24.w, z);
            z += __shfl_xor_sync(FM, z, 8);
            z += __shfl_xor_sync(FM, z, 4);
            z += __shfl_xor_sync(FM, z, 2);
            z += __shfl_xor_sync(FM, z, 1);
            if (l16 == 0) s_xy[w][2 * i + g] = z;
        }
        __syncwarp();

        // ---- phase 4: sigmoid (lane = edge) ----
        s_sc[w][lane] = sigmoidf_(s_xy[w][lane] + b2s) * em;   // em=0 on tail
        __syncwarp();

        // ---- phase 5: scatter ----
#pragma unroll 4
        for (int i = 0; i < 16; ++i) {
            int er = s_r[w][2 * i + g], ec = s_c[w][2 * i + g];
            float s = s_sc[w][2 * i + g];
            float4 xc = g_xt4[ec * 16 + l16];
            red_add_v4(&g_agg[er * 64 + l16 * 4],
                       xc.x * s, xc.y * s, xc.z * s, xc.w * s);
        }
    }
}

// ===== K3 (thread-per-node): MLP + expmap0/logmap0/silu epilogue ============
__global__ void __launch_bounds__(128)
k_node3(const float* __restrict__ Wm1,
        const float* __restrict__ bm1,
        const float* __restrict__ Wm2,
        const float* __restrict__ bm2,
        float* __restrict__ out, int n) {
    __shared__ float sW1t[64 * WSTRIDE];
    __shared__ float sW2t[64 * WSTRIDE];
    __shared__ float sb1[64];
    __shared__ float sb2[64];

    const int tid = threadIdx.x;
    for (int idx = tid; idx < 4096; idx += 128) {
        int o = idx >> 6, k = idx & 63;
        sW1t[k * WSTRIDE + o] = Wm1[idx];
        sW2t[k * WSTRIDE + o] = Wm2[idx];
    }
    if (tid < 64) { sb1[tid] = bm1[tid]; sb2[tid] = bm2[tid]; }
    __syncthreads();

    int node = blockIdx.x * 128 + tid;
    bool valid = node < n;
    int nd = valid ? node : 0;

    // agg / 100
    const float4* gag = reinterpret_cast<const float4*>(g_agg) + (size_t)nd * 16;
    float aloc[64];
#pragma unroll
    for (int i = 0; i < 16; ++i) {
        float4 v = gag[i];
        aloc[4 * i + 0] = v.x * 0.01f; aloc[4 * i + 1] = v.y * 0.01f;
        aloc[4 * i + 2] = v.z * 0.01f; aloc[4 * i + 3] = v.w * 0.01f;
    }

    // GEMV1 + bias + silu
    float4 acc[16];
#pragma unroll
    for (int i = 0; i < 16; ++i) acc[i] = make_float4(0.f, 0.f, 0.f, 0.f);
#pragma unroll 4
    for (int k = 0; k < 64; ++k) {
        float xk = aloc[k];
        const float4* wr = reinterpret_cast<const float4*>(sW1t + k * WSTRIDE);
#pragma unroll
        for (int j = 0; j < 16; ++j) {
            float4 w4 = wr[j];
            acc[j].x = fmaf(w4.x, xk, acc[j].x);
            acc[j].y = fmaf(w4.y, xk, acc[j].y);
            acc[j].z = fmaf(w4.z, xk, acc[j].z);
            acc[j].w = fmaf(w4.w, xk, acc[j].w);
        }
    }
    float hloc[64];
#pragma unroll
    for (int i = 0; i < 16; ++i) {
        float4 b4 = *reinterpret_cast<const float4*>(sb1 + 4 * i);
        hloc[4 * i + 0] = siluf_(acc[i].x + b4.x);
        hloc[4 * i + 1] = siluf_(acc[i].y + b4.y);
        hloc[4 * i + 2] = siluf_(acc[i].z + b4.z);
        hloc[4 * i + 3] = siluf_(acc[i].w + b4.w);
    }

    // GEMV2
#pragma unroll
    for (int i = 0; i < 16; ++i) acc[i] = make_float4(0.f, 0.f, 0.f, 0.f);
#pragma unroll 4
    for (int k = 0; k < 64; ++k) {
        float xk = hloc[k];
        const float4* wr = reinterpret_cast<const float4*>(sW2t + k * WSTRIDE);
#pragma unroll
        for (int j = 0; j < 16; ++j) {
            float4 w4 = wr[j];
            acc[j].x = fmaf(w4.x, xk, acc[j].x);
            acc[j].y = fmaf(w4.y, xk, acc[j].y);
            acc[j].z = fmaf(w4.z, xk, acc[j].z);
            acc[j].w = fmaf(w4.w, xk, acc[j].w);
        }
    }

    // y = xtan + mlp ; epilogue
    const float4* gxt = g_xt4 + (size_t)nd * 16;
    float ysq = 0.f;
#pragma unroll
    for (int i = 0; i < 16; ++i) {
        float4 b4 = *reinterpret_cast<const float4*>(sb2 + 4 * i);
        float4 xt = gxt[i];
        acc[i].x += b4.x + xt.x;
        acc[i].y += b4.y + xt.y;
        acc[i].z += b4.z + xt.z;
        acc[i].w += b4.w + xt.w;
        ysq += acc[i].x * acc[i].x + acc[i].y * acc[i].y + acc[i].z * acc[i].z + acc[i].w * acc[i].w;
    }

    float ny = fmaxf(sqrtf(ysq), EPSV);
    float t = tanh_pos(ny);
    float s1 = t * __fdividef(1.0f, ny);          // expmap0 scale
    float no = fmaxf(t, EPSV);                    // ||o1|| = tanh(ny)
    float a2 = artanh_c(no) * __fdividef(1.0f, no);
    float sc = s1 * a2;                           // t2 = sc * y

    float ssq = 0.f;
    float4 sl[16];
#pragma unroll
    for (int i = 0; i < 16; ++i) {
        sl[i].x = siluf_(acc[i].x * sc);
        sl[i].y = siluf_(acc[i].y * sc);
        sl[i].z = siluf_(acc[i].z * sc);
        sl[i].w = siluf_(acc[i].w * sc);
        ssq += sl[i].x * sl[i].x + sl[i].y * sl[i].y + sl[i].z * sl[i].z + sl[i].w * sl[i].w;
    }
    float ns = fmaxf(sqrtf(ssq), EPSV);
    float s3 = tanh_pos(ns) * __fdividef(1.0f, ns);

    float4* op = reinterpret_cast<float4*>(out) + (size_t)nd * 16;
#pragma unroll
    for (int i = 0; i < 16; ++i)
        if (valid)
            op[i] = make_float4(sl[i].x * s3, sl[i].y * s3, sl[i].z * s3, sl[i].w * s3);
}

// ------------------------------- launch -------------------------------------
extern "C" void kernel_launch(void* const* d_in, const int* in_sizes, int n_in,
                              void* d_out, int out_size) {
    const float* h         = (const float*)d_in[0];
    const float* distances = (const float*)d_in[1];
    const int*   edges     = (const int*)  d_in[2];
    // d_in[3] = node_mask (unused by reference)
    const float* edge_mask = (const float*)d_in[4];
    const float* W_lin     = (const float*)d_in[5];
    const float* b_lin     = (const float*)d_in[6];
    const float* Wa1       = (const float*)d_in[7];
    const float* ba1       = (const float*)d_in[8];
    const float* Wa2       = (const float*)d_in[9];
    const float* ba2       = (const float*)d_in[10];
    const float* Wm1       = (const float*)d_in[11];
    const float* bm1       = (const float*)d_in[12];
    const float* Wm2       = (const float*)d_in[13];
    const float* bm2       = (const float*)d_in[14];

    int N = in_sizes[0] / 64;
    int E = in_sizes[1];

    int blocksN = (N + 127) / 128;
    size_t smA = (3 * 64 * WSTRIDE + 128) * sizeof(float);   // 52736 B

    static bool attr_set = false;
    if (!attr_set) {
        cudaFuncSetAttribute(k_nodeA, cudaFuncAttributeMaxDynamicSharedMemorySize, (int)smA);
        attr_set = true;
    }

    k_nodeA<<<blocksN, 128, smA>>>(h, W_lin, b_lin, Wa1, ba1, N);
    k_edge<<<2048, 256>>>(edges, distances, edge_mask, Wa1, Wa2, ba2, E);
    k_node3<<<blocksN, 128>>>(Wm1, bm1, Wm2, bm2, (float*)d_out, N);
}

// round 6
// speedup vs baseline: 1.7025x; 1.0111x over previous
#include <cuda_runtime.h>
#include <cuda_bf16.h>

#define EPSV 1e-7f
#define MAXN 50000
#define WSTRIDE 68   // transposed weight row stride (floats), 16B-aligned

// ------------------------- static device scratch ---------------------------
__device__ __align__(16) float4 g_hb4[MAXN * 16];   // fp32 hb (for k_pq)
__device__ __align__(16) float4 g_xt4[MAXN * 16];   // fp32 xtan (for k_node3)
__device__ float g_nsq[MAXN];
__device__ __align__(16) float g_agg[MAXN * 64];    // fp32 accumulators
// bf16 tables for the edge kernel (4 dims per uint2)
__device__ __align__(16) uint2 g_hbh[MAXN * 16];
__device__ __align__(16) uint2 g_Ph [MAXN * 16];
__device__ __align__(16) uint2 g_Qh [MAXN * 16];
__device__ __align__(16) uint2 g_xth[MAXN * 16];

// ------------------------------ helpers ------------------------------------
__device__ __forceinline__ float artanh_c(float x) {
    x = fminf(x, 1.0f - EPSV);
    return 0.5f * __logf(__fdividef(1.0f + x, 1.0f - x));
}
__device__ __forceinline__ float tanh_pos(float x) {  // x >= 0
    float e = __expf(-2.0f * x);
    return (1.0f - e) * __fdividef(1.0f, 1.0f + e);
}
__device__ __forceinline__ float sigmoidf_(float z) {
    return __fdividef(1.0f, 1.0f + __expf(-z));
}
__device__ __forceinline__ float siluf_(float z) {
    return z * sigmoidf_(z);
}
__device__ __forceinline__ void red_add_v4(float* a, float x, float y, float z, float w) {
    asm volatile("red.global.add.v4.f32 [%0], {%1, %2, %3, %4};"
                 :: "l"(a), "f"(x), "f"(y), "f"(z), "f"(w) : "memory");
}
__device__ __forceinline__ unsigned pk2(float a, float b) {
    __nv_bfloat162 t = __floats2bfloat162_rn(a, b);
    return *reinterpret_cast<unsigned*>(&t);
}
__device__ __forceinline__ float2 upk(unsigned u) {
    __nv_bfloat162 t = *reinterpret_cast<__nv_bfloat162*>(&u);
    return __bfloat1622float2(t);
}

// ===== K1: HypLinear (thread-per-node): h -> hb, nsq, xtan, zero agg ========
__global__ void __launch_bounds__(128)
k_hyp(const float* __restrict__ h,
      const float* __restrict__ Wlin,
      const float* __restrict__ blin, int n) {
    __shared__ float sWt[64 * WSTRIDE];   // sWt[k*WS+o] = Wlin[o][k]
    __shared__ __align__(16) float sbl[64];

    const int tid = threadIdx.x;
    for (int idx = tid; idx < 4096; idx += 128) {
        int o = idx >> 6, k = idx & 63;
        sWt[k * WSTRIDE + o] = Wlin[idx];
    }
    if (tid < 64) sbl[tid] = blin[tid];
    __syncthreads();

    int node = blockIdx.x * 128 + tid;
    bool valid = node < n;
    int nd = valid ? node : 0;

    // load h, ||h||^2, stage lm = artanh(|h|)/|h| * h
    const float4* hp = reinterpret_cast<const float4*>(h) + (size_t)nd * 16;
    float xloc[64];
    float hsq = 0.f;
#pragma unroll
    for (int i = 0; i < 16; ++i) {
        float4 v = hp[i];
        hsq += v.x * v.x + v.y * v.y + v.z * v.z + v.w * v.w;
        xloc[4 * i + 0] = v.x; xloc[4 * i + 1] = v.y;
        xloc[4 * i + 2] = v.z; xloc[4 * i + 3] = v.w;
    }
    float nh = fmaxf(sqrtf(hsq), EPSV);
    float a = artanh_c(nh) * __fdividef(1.0f, nh);
#pragma unroll
    for (int i = 0; i < 64; ++i) xloc[i] *= a;

    // GEMV: acc = lm @ Wlin.T (uniform broadcast weights)
    float4 acc[16];
#pragma unroll
    for (int i = 0; i < 16; ++i) acc[i] = make_float4(0.f, 0.f, 0.f, 0.f);
#pragma unroll 4
    for (int k = 0; k < 64; ++k) {
        float xk = xloc[k];
        const float4* wr = reinterpret_cast<const float4*>(sWt + k * WSTRIDE);
#pragma unroll
        for (int j = 0; j < 16; ++j) {
            float4 w4 = wr[j];
            acc[j].x = fmaf(w4.x, xk, acc[j].x);
            acc[j].y = fmaf(w4.y, xk, acc[j].y);
            acc[j].z = fmaf(w4.z, xk, acc[j].z);
            acc[j].w = fmaf(w4.w, xk, acc[j].w);
        }
    }

    // scalar hyperbolic chain (per-thread, no reductions)
    float xsq = 0.f;
#pragma unroll
    for (int i = 0; i < 16; ++i)
        xsq += acc[i].x * acc[i].x + acc[i].y * acc[i].y + acc[i].z * acc[i].z + acc[i].w * acc[i].w;
    float nx = fmaxf(sqrtf(xsq), EPSV);
    float s0 = tanh_pos(nx) * __fdividef(1.0f, nx);
    float res2 = xsq * s0 * s0;
    float omr = 1.0f - res2;

    float bsq = 0.f, rb = 0.f;
    const float4* sbl4 = reinterpret_cast<const float4*>(sbl);
#pragma unroll
    for (int i = 0; i < 16; ++i) {
        float4 b4 = sbl4[i];
        bsq += b4.x * b4.x + b4.y * b4.y + b4.z * b4.z + b4.w * b4.w;
        rb  += acc[i].x * b4.x + acc[i].y * b4.y + acc[i].z * b4.z + acc[i].w * b4.w;
    }
    rb *= s0;

    float usq = bsq * omr * omr;
    float nu = fmaxf(sqrtf(usq), EPSV);
    float lam = 2.0f * __fdividef(1.0f, fmaxf(omr, EPSV));
    float ws = tanh_pos(0.5f * lam * nu) * __fdividef(1.0f, nu);
    float y2 = usq * ws * ws;
    float xy = ws * omr * rb;
    float ca = 1.0f + 2.0f * xy + y2;
    float den = fmaxf(1.0f + 2.0f * xy + res2 * y2, EPSV);
    float inv = __fdividef(1.0f, den);
    float c1 = ca * s0 * inv;          // multiplies raw acc
    float c2 = omr * omr * ws * inv;   // multiplies b

    // hb, norms
    float hbsq = 0.f;
#pragma unroll
    for (int i = 0; i < 16; ++i) {
        float4 b4 = sbl4[i];
        acc[i].x = c1 * acc[i].x + c2 * b4.x;
        acc[i].y = c1 * acc[i].y + c2 * b4.y;
        acc[i].z = c1 * acc[i].z + c2 * b4.z;
        acc[i].w = c1 * acc[i].w + c2 * b4.w;
        hbsq += acc[i].x * acc[i].x + acc[i].y * acc[i].y + acc[i].z * acc[i].z + acc[i].w * acc[i].w;
    }
    float nb = fmaxf(sqrtf(hbsq), EPSV);
    float at = artanh_c(nb) * __fdividef(1.0f, nb);

    if (valid) {
        g_nsq[nd] = hbsq;
        float4* ghb = g_hb4 + (size_t)nd * 16;
        float4* gxt = g_xt4 + (size_t)nd * 16;
        float4* gag = reinterpret_cast<float4*>(g_agg) + (size_t)nd * 16;
        uint2*  gbh = g_hbh + (size_t)nd * 16;
        uint2*  gth = g_xth + (size_t)nd * 16;
#pragma unroll
        for (int i = 0; i < 16; ++i) {
            float4 hb = acc[i];
            float4 xt = make_float4(hb.x * at, hb.y * at, hb.z * at, hb.w * at);
            ghb[i] = hb;
            gxt[i] = xt;
            gbh[i] = make_uint2(pk2(hb.x, hb.y), pk2(hb.z, hb.w));
            gth[i] = make_uint2(pk2(xt.x, xt.y), pk2(xt.z, xt.w));
            gag[i] = make_float4(0.f, 0.f, 0.f, 0.f);
        }
    }
}

// ===== K2: P = hb@A.T + ba1, Q = hb@B.T (thread-per-node, sequential) =======
__global__ void __launch_bounds__(128)
k_pq(const float* __restrict__ Wa1,
     const float* __restrict__ ba1, int n) {
    __shared__ float sAt[64 * WSTRIDE];
    __shared__ float sBt[64 * WSTRIDE];
    __shared__ __align__(16) float sb1[64];

    const int tid = threadIdx.x;
    for (int idx = tid; idx < 8192; idx += 128) {
        int half = idx >> 12, o = (idx >> 6) & 63, k = idx & 63;
        float v = Wa1[o * 130 + half * 64 + k];
        (half ? sBt : sAt)[k * WSTRIDE + o] = v;
    }
    if (tid < 64) sb1[tid] = ba1[tid];
    __syncthreads();

    int node = blockIdx.x * 128 + tid;
    bool valid = node < n;
    int nd = valid ? node : 0;

    // stage hb in local
    const float4* ghb = g_hb4 + (size_t)nd * 16;
    float hloc[64];
#pragma unroll
    for (int i = 0; i < 16; ++i) {
        float4 v = ghb[i];
        hloc[4 * i + 0] = v.x; hloc[4 * i + 1] = v.y;
        hloc[4 * i + 2] = v.z; hloc[4 * i + 3] = v.w;
    }

    float4 acc[16];
    // ---- GEMV P ----
#pragma unroll
    for (int i = 0; i < 16; ++i) acc[i] = make_float4(0.f, 0.f, 0.f, 0.f);
#pragma unroll 4
    for (int k = 0; k < 64; ++k) {
        float hk = hloc[k];
        const float4* wr = reinterpret_cast<const float4*>(sAt + k * WSTRIDE);
#pragma unroll
        for (int j = 0; j < 16; ++j) {
            float4 w4 = wr[j];
            acc[j].x = fmaf(w4.x, hk, acc[j].x);
            acc[j].y = fmaf(w4.y, hk, acc[j].y);
            acc[j].z = fmaf(w4.z, hk, acc[j].z);
            acc[j].w = fmaf(w4.w, hk, acc[j].w);
        }
    }
    if (valid) {
        const float4* sb14 = reinterpret_cast<const float4*>(sb1);
        uint2* gp = g_Ph + (size_t)nd * 16;
#pragma unroll
        for (int i = 0; i < 16; ++i) {
            float4 b4 = sb14[i];
            gp[i] = make_uint2(pk2(acc[i].x + b4.x, acc[i].y + b4.y),
                               pk2(acc[i].z + b4.z, acc[i].w + b4.w));
        }
    }

    // ---- GEMV Q ----
#pragma unroll
    for (int i = 0; i < 16; ++i) acc[i] = make_float4(0.f, 0.f, 0.f, 0.f);
#pragma unroll 4
    for (int k = 0; k < 64; ++k) {
        float hk = hloc[k];
        const float4* wr = reinterpret_cast<const float4*>(sBt + k * WSTRIDE);
#pragma unroll
        for (int j = 0; j < 16; ++j) {
            float4 w4 = wr[j];
            acc[j].x = fmaf(w4.x, hk, acc[j].x);
            acc[j].y = fmaf(w4.y, hk, acc[j].y);
            acc[j].z = fmaf(w4.z, hk, acc[j].z);
            acc[j].w = fmaf(w4.w, hk, acc[j].w);
        }
    }
    if (valid) {
        uint2* gq = g_Qh + (size_t)nd * 16;
#pragma unroll
        for (int i = 0; i < 16; ++i)
            gq[i] = make_uint2(pk2(acc[i].x, acc[i].y), pk2(acc[i].z, acc[i].w));
    }
}

// ========== K3: edge attention + scatter (16 lanes/edge, bf16 tables) =======
__global__ void __launch_bounds__(256)
k_edge(const int* __restrict__ edges,
       const float* __restrict__ dist,
       const float* __restrict__ emask,
       const float* __restrict__ Wa1,
       const float* __restrict__ Wa2,
       const float* __restrict__ ba2, int E) {
    __shared__ int   s_r [8][32];
    __shared__ int   s_c [8][32];
    __shared__ float s_xy[8][32];
    __shared__ float s_dh[8][32];
    __shared__ float s_dd[8][32];
    __shared__ float s_sc[8][32];

    const int lane = threadIdx.x & 31, w = threadIdx.x >> 5;
    const int g = lane >> 4, l16 = lane & 15;
    const unsigned FM = 0xffffffffu;

    float4 wd4  = make_float4(Wa1[(4 * l16 + 0) * 130 + 128], Wa1[(4 * l16 + 1) * 130 + 128],
                              Wa1[(4 * l16 + 2) * 130 + 128], Wa1[(4 * l16 + 3) * 130 + 128]);
    float4 wdd4 = make_float4(Wa1[(4 * l16 + 0) * 130 + 129], Wa1[(4 * l16 + 1) * 130 + 129],
                              Wa1[(4 * l16 + 2) * 130 + 129], Wa1[(4 * l16 + 3) * 130 + 129]);
    float4 wa24 = make_float4(Wa2[4 * l16 + 0], Wa2[4 * l16 + 1],
                              Wa2[4 * l16 + 2], Wa2[4 * l16 + 3]);
    float b2s = ba2[0];

    const int chunks = (E + 31) >> 5;
    for (int ch = blockIdx.x * 8 + w; ch < chunks; ch += gridDim.x * 8) {
        int e = ch * 32 + lane;
        bool v = e < E;
        int r = 0, c = 0;
        float dd = 0.f, em = 0.f, sr = 0.f, sc_ = 0.f;
        if (v) {
            r = edges[e];
            c = edges[E + e];
            dd = dist[e];
            em = emask[e];
            sr = g_nsq[r];
            sc_ = g_nsq[c];
        }
        __syncwarp();
        s_r[w][lane] = r; s_c[w][lane] = c; s_dd[w][lane] = dd;
        __syncwarp();

        // ---- phase 1: per-edge dot xy (2 edges / iteration, bf16 loads) ----
#pragma unroll 4
        for (int i = 0; i < 16; ++i) {
            int er = s_r[w][2 * i + g], ec = s_c[w][2 * i + g];
            uint2 hr = g_hbh[er * 16 + l16];
            uint2 hc = g_hbh[ec * 16 + l16];
            float2 a0 = upk(hr.x), a1 = upk(hr.y);
            float2 b0 = upk(hc.x), b1 = upk(hc.y);
            float d = a0.x * b0.x + a0.y * b0.y + a1.x * b1.x + a1.y * b1.y;
            d += __shfl_xor_sync(FM, d, 8);
            d += __shfl_xor_sync(FM, d, 4);
            d += __shfl_xor_sync(FM, d, 2);
            d += __shfl_xor_sync(FM, d, 1);
            if (l16 == 0) s_xy[w][2 * i + g] = d;
        }
        __syncwarp();

        // ---- phase 2: hyperbolic distance (lane = edge) ----
        {
            float xyv = s_xy[w][lane];
            float al = 1.0f - 2.0f * xyv + sc_;
            float be = 1.0f - sr;
            float num2 = al * al * sr + be * be * sc_ - 2.0f * al * be * xyv;
            float den = fmaxf(1.0f - 2.0f * xyv + sr * sc_, EPSV);
            float nrm = __fdividef(sqrtf(fmaxf(num2, 0.0f)), den);
            s_dh[w][lane] = 2.0f * artanh_c(nrm);
        }
        __syncwarp();

        // ---- phase 3: hidden layer + z ----
#pragma unroll 4
        for (int i = 0; i < 16; ++i) {
            int er = s_r[w][2 * i + g], ec = s_c[w][2 * i + g];
            float dh = s_dh[w][2 * i + g], di = s_dd[w][2 * i + g];
            uint2 pu = g_Ph[er * 16 + l16];
            uint2 qu = g_Qh[ec * 16 + l16];
            float2 p0 = upk(pu.x), p1 = upk(pu.y);
            float2 q0 = upk(qu.x), q1 = upk(qu.y);
            float hx = fmaf(di, wdd4.x, fmaf(dh, wd4.x, p0.x + q0.x));
            float hy = fmaf(di, wdd4.y, fmaf(dh, wd4.y, p0.y + q0.y));
            float hz = fmaf(di, wdd4.z, fmaf(dh, wd4.z, p1.x + q1.x));
            float hw = fmaf(di, wdd4.w, fmaf(dh, wd4.w, p1.y + q1.y));
            float z = siluf_(hx) * wa24.x;
            z = fmaf(siluf_(hy), wa24.y, z);
            z = fmaf(siluf_(hz), wa24.z, z);
            z = fmaf(siluf_(hw), wa24.w, z);
            z += __shfl_xor_sync(FM, z, 8);
            z += __shfl_xor_sync(FM, z, 4);
            z += __shfl_xor_sync(FM, z, 2);
            z += __shfl_xor_sync(FM, z, 1);
            if (l16 == 0) s_xy[w][2 * i + g] = z;
        }
        __syncwarp();

        // ---- phase 4: sigmoid (lane = edge) ----
        s_sc[w][lane] = sigmoidf_(s_xy[w][lane] + b2s) * em;   // em=0 on tail
        __syncwarp();

        // ---- phase 5: scatter ----
#pragma unroll 4
        for (int i = 0; i < 16; ++i) {
            int er = s_r[w][2 * i + g], ec = s_c[w][2 * i + g];
            float s = s_sc[w][2 * i + g];
            uint2 xu = g_xth[ec * 16 + l16];
            float2 x0 = upk(xu.x), x1 = upk(xu.y);
            red_add_v4(&g_agg[er * 64 + l16 * 4],
                       x0.x * s, x0.y * s, x1.x * s, x1.y * s);
        }
    }
}

// ===== K4 (thread-per-node): MLP + expmap0/logmap0/silu epilogue ============
__global__ void __launch_bounds__(128)
k_node3(const float* __restrict__ Wm1,
        const float* __restrict__ bm1,
        const float* __restrict__ Wm2,
        const float* __restrict__ bm2,
        float* __restrict__ out, int n) {
    __shared__ float sW1t[64 * WSTRIDE];
    __shared__ float sW2t[64 * WSTRIDE];
    __shared__ __align__(16) float sb1[64];
    __shared__ __align__(16) float sb2[64];

    const int tid = threadIdx.x;
    for (int idx = tid; idx < 4096; idx += 128) {
        int o = idx >> 6, k = idx & 63;
        sW1t[k * WSTRIDE + o] = Wm1[idx];
        sW2t[k * WSTRIDE + o] = Wm2[idx];
    }
    if (tid < 64) { sb1[tid] = bm1[tid]; sb2[tid] = bm2[tid]; }
    __syncthreads();

    int node = blockIdx.x * 128 + tid;
    bool valid = node < n;
    int nd = valid ? node : 0;

    const float4* gag = reinterpret_cast<const float4*>(g_agg) + (size_t)nd * 16;
    float aloc[64];
#pragma unroll
    for (int i = 0; i < 16; ++i) {
        float4 v = gag[i];
        aloc[4 * i + 0] = v.x * 0.01f; aloc[4 * i + 1] = v.y * 0.01f;
        aloc[4 * i + 2] = v.z * 0.01f; aloc[4 * i + 3] = v.w * 0.01f;
    }

    float4 acc[16];
#pragma unroll
    for (int i = 0; i < 16; ++i) acc[i] = make_float4(0.f, 0.f, 0.f, 0.f);
#pragma unroll 4
    for (int k = 0; k < 64; ++k) {
        float xk = aloc[k];
        const float4* wr = reinterpret_cast<const float4*>(sW1t + k * WSTRIDE);
#pragma unroll
        for (int j = 0; j < 16; ++j) {
            float4 w4 = wr[j];
            acc[j].x = fmaf(w4.x, xk, acc[j].x);
            acc[j].y = fmaf(w4.y, xk, acc[j].y);
            acc[j].z = fmaf(w4.z, xk, acc[j].z);
            acc[j].w = fmaf(w4.w, xk, acc[j].w);
        }
    }
    float hloc[64];
    const float4* sb14 = reinterpret_cast<const float4*>(sb1);
#pragma unroll
    for (int i = 0; i < 16; ++i) {
        float4 b4 = sb14[i];
        hloc[4 * i + 0] = siluf_(acc[i].x + b4.x);
        hloc[4 * i + 1] = siluf_(acc[i].y + b4.y);
        hloc[4 * i + 2] = siluf_(acc[i].z + b4.z);
        hloc[4 * i + 3] = siluf_(acc[i].w + b4.w);
    }

#pragma unroll
    for (int i = 0; i < 16; ++i) acc[i] = make_float4(0.f, 0.f, 0.f, 0.f);
#pragma unroll 4
    for (int k = 0; k < 64; ++k) {
        float xk = hloc[k];
        const float4* wr = reinterpret_cast<const float4*>(sW2t + k * WSTRIDE);
#pragma unroll
        for (int j = 0; j < 16; ++j) {
            float4 w4 = wr[j];
            acc[j].x = fmaf(w4.x, xk, acc[j].x);
            acc[j].y = fmaf(w4.y, xk, acc[j].y);
            acc[j].z = fmaf(w4.z, xk, acc[j].z);
            acc[j].w = fmaf(w4.w, xk, acc[j].w);
        }
    }

    const float4* gxt = g_xt4 + (size_t)nd * 16;
    const float4* sb24 = reinterpret_cast<const float4*>(sb2);
    float ysq = 0.f;
#pragma unroll
    for (int i = 0; i < 16; ++i) {
        float4 b4 = sb24[i];
        float4 xt = gxt[i];
        acc[i].x += b4.x + xt.x;
        acc[i].y += b4.y + xt.y;
        acc[i].z += b4.z + xt.z;
        acc[i].w += b4.w + xt.w;
        ysq += acc[i].x * acc[i].x + acc[i].y * acc[i].y + acc[i].z * acc[i].z + acc[i].w * acc[i].w;
    }

    float ny = fmaxf(sqrtf(ysq), EPSV);
    float t = tanh_pos(ny);
    float s1 = t * __fdividef(1.0f, ny);
    float no = fmaxf(t, EPSV);                    // ||expmap0(y)|| = tanh(ny)
    float a2 = artanh_c(no) * __fdividef(1.0f, no);
    float sc = s1 * a2;

    float ssq = 0.f;
    float4 sl[16];
#pragma unroll
    for (int i = 0; i < 16; ++i) {
        sl[i].x = siluf_(acc[i].x * sc);
        sl[i].y = siluf_(acc[i].y * sc);
        sl[i].z = siluf_(acc[i].z * sc);
        sl[i].w = siluf_(acc[i].w * sc);
        ssq += sl[i].x * sl[i].x + sl[i].y * sl[i].y + sl[i].z * sl[i].z + sl[i].w * sl[i].w;
    }
    float ns = fmaxf(sqrtf(ssq), EPSV);
    float s3 = tanh_pos(ns) * __fdividef(1.0f, ns);

    if (valid) {
        float4* op = reinterpret_cast<float4*>(out) + (size_t)nd * 16;
#pragma unroll
        for (int i = 0; i < 16; ++i)
            op[i] = make_float4(sl[i].x * s3, sl[i].y * s3, sl[i].z * s3, sl[i].w * s3);
    }
}

// ------------------------------- launch -------------------------------------
extern "C" void kernel_launch(void* const* d_in, const int* in_sizes, int n_in,
                              void* d_out, int out_size) {
    const float* h         = (const float*)d_in[0];
    const float* distances = (const float*)d_in[1];
    const int*   edges     = (const int*)  d_in[2];
    // d_in[3] = node_mask (unused by reference)
    const float* edge_mask = (const float*)d_in[4];
    const float* W_lin     = (const float*)d_in[5];
    const float* b_lin     = (const float*)d_in[6];
    const float* Wa1       = (const float*)d_in[7];
    const float* ba1       = (const float*)d_in[8];
    const float* Wa2       = (const float*)d_in[9];
    const float* ba2       = (const float*)d_in[10];
    const float* Wm1       = (const float*)d_in[11];
    const float* bm1       = (const float*)d_in[12];
    const float* Wm2       = (const float*)d_in[13];
    const float* bm2       = (const float*)d_in[14];

    int N = in_sizes[0] / 64;
    int E = in_sizes[1];

    int blocksN = (N + 127) / 128;

    k_hyp  <<<blocksN, 128>>>(h, W_lin, b_lin, N);
    k_pq   <<<blocksN, 128>>>(Wa1, ba1, N);
    k_edge <<<2048, 256>>>(edges, distances, edge_mask, Wa1, Wa2, ba2, E);
    k_node3<<<blocksN, 128>>>(Wm1, bm1, Wm2, bm2, (float*)d_out, N);
}